// round 1
// baseline (speedup 1.0000x reference)
#include <cuda_runtime.h>

#define NB 32
#define NC 64
#define NS 128
#define NZ 64
#define ND 256

// ---------------- device scratch (no allocations allowed) ----------------
__device__ float g_am [NB*NS*ND];   // relu(a@FW + Fb)
__device__ float g_aG1[NB*NS*ND];   // a@GW1 + Gb
__device__ float g_aG2[NB*NS*ND];   // a@GW2

// =========================================================================
// Stage 1: per batch b, gather a = EmbA[inp[b]], compute a_m / aG1 / aG2.
// grid = (12, 32): blockIdx.x = chunk (3 matrices x 4 g-chunks of 64),
// blockIdx.y = b.  256 threads.
// smem: a_tile[128][257] + wst[16][64]
// =========================================================================
__global__ void __launch_bounds__(256) stage1_kernel(
    const int*   __restrict__ inptensor,
    const float* __restrict__ EmbA,
    const float* __restrict__ FW,
    const float* __restrict__ Fb,
    const float* __restrict__ GW,
    const float* __restrict__ Gb)
{
    extern __shared__ float sm[];
    float* a_tile = sm;              // 128*257 floats
    float* wst    = sm + 128*257;    // 16*64 floats

    const int b     = blockIdx.y;
    const int chunk = blockIdx.x;
    const int m     = chunk >> 2;          // 0: a_m, 1: aG1, 2: aG2
    const int gbase = (chunk & 3) * 64;
    const int tid   = threadIdx.x;

    // gather a: row s, col tid
    for (int s = 0; s < NS; s++) {
        int idx = __ldg(&inptensor[b*NS + s]);
        a_tile[s*257 + tid] = __ldg(&EmbA[idx*ND + tid]);
    }
    __syncthreads();

    const int tr = tid >> 3;   // 0..31 (s groups)
    const int tc = tid & 7;    // 0..7  (g groups)

    float acc[4][8];
    #pragma unroll
    for (int i = 0; i < 4; i++)
        #pragma unroll
        for (int j = 0; j < 8; j++) acc[i][j] = 0.f;

    for (int k0 = 0; k0 < ND; k0 += 16) {
        // stage weight tile [16][64]
        #pragma unroll
        for (int t = 0; t < 4; t++) {
            int idx2 = tid + 256*t;
            int kk = idx2 >> 6, gg = idx2 & 63;
            int row = k0 + kk + (m == 2 ? 256 : 0);
            const float* Wsrc = (m == 0) ? FW : GW;
            wst[idx2] = __ldg(&Wsrc[row*256 + gbase + gg]);
        }
        __syncthreads();
        #pragma unroll
        for (int kk = 0; kk < 16; kk++) {
            float av[4], wv[8];
            #pragma unroll
            for (int i = 0; i < 4; i++) av[i] = a_tile[(tr + 32*i)*257 + k0 + kk];
            #pragma unroll
            for (int j = 0; j < 8; j++) wv[j] = wst[kk*64 + tc + 8*j];
            #pragma unroll
            for (int i = 0; i < 4; i++)
                #pragma unroll
                for (int j = 0; j < 8; j++) acc[i][j] += av[i]*wv[j];
        }
        __syncthreads();
    }

    float* outp = (m == 0) ? g_am : (m == 1 ? g_aG1 : g_aG2);
    #pragma unroll
    for (int j = 0; j < 8; j++) {
        int g = gbase + tc + 8*j;
        float bias = (m == 0) ? __ldg(&Fb[g]) : (m == 1 ? __ldg(&Gb[g]) : 0.f);
        #pragma unroll
        for (int i = 0; i < 4; i++) {
            float v = acc[i][j] + bias;
            if (m == 0) v = fmaxf(v, 0.f);
            outp[(b*NS + tr + 32*i)*ND + g] = v;
        }
    }
}

// =========================================================================
// Stage 2: one CTA per (b,c). 256 threads. dynamic smem layout (floats):
//   s_bb  @ 0      : [64][257]   raw bb embeddings          (16448)
//   s_bm  @ 16448  : [64][257]   b_m; later beta[128][65] + P5 staging
//   s_e   @ 32896  : [128][65]   e logits -> alpha in place  (8320)
//   s_buf @ 41216  : [64][256]   staging / bbG2             (16384)
// total 57600 floats = 230400 B
// =========================================================================
__global__ void __launch_bounds__(256) pair_kernel(
    const int*   __restrict__ cand,
    const float* __restrict__ EmbB,
    const float* __restrict__ FW,
    const float* __restrict__ Fb,
    const float* __restrict__ GW,
    const float* __restrict__ Gb,
    const float* __restrict__ HW,
    const float* __restrict__ Hb,
    float*       __restrict__ out)
{
    extern __shared__ float sm[];
    float* s_bb   = sm;                 // [64][257]
    float* s_bm   = sm + 16448;         // [64][257]
    float* s_e    = sm + 32896;         // [128][65]
    float* s_buf  = sm + 41216;         // [64][256]
    float* s_beta = s_bm;               // [128][65] (after P3)
    float* s_st5  = s_bm + 8320;        // P5 weight staging [16][256]

    const int tid = threadIdx.x;
    const int p   = blockIdx.x;
    const int b   = p >> 6;

    // ---- P1: gather bb = EmbB[cand[b,c,:]] ----
    {
        const int* ci = cand + p*NZ;
        for (int z = 0; z < NZ; z++) {
            int idx = __ldg(&ci[z]);
            s_bb[z*257 + tid] = __ldg(&EmbB[idx*ND + tid]);
        }
    }
    __syncthreads();

    // ---- P2: b_m = relu(bb @ FW + Fb)  (64x256, K=256) ----
    {
        const int tr = tid >> 5, tc = tid & 31;
        float acc[8][8];
        #pragma unroll
        for (int i = 0; i < 8; i++)
            #pragma unroll
            for (int j = 0; j < 8; j++) acc[i][j] = 0.f;

        for (int k0 = 0; k0 < ND; k0 += 16) {
            #pragma unroll
            for (int t = 0; t < 16; t++)
                s_buf[t*256 + tid] = __ldg(&FW[(k0 + t)*256 + tid]);
            __syncthreads();
            #pragma unroll
            for (int kk = 0; kk < 16; kk++) {
                float bv[8], wv[8];
                #pragma unroll
                for (int i = 0; i < 8; i++) bv[i] = s_bb[(tr + 8*i)*257 + k0 + kk];
                #pragma unroll
                for (int j = 0; j < 8; j++) wv[j] = s_buf[kk*256 + tc + 32*j];
                #pragma unroll
                for (int i = 0; i < 8; i++)
                    #pragma unroll
                    for (int j = 0; j < 8; j++) acc[i][j] += bv[i]*wv[j];
            }
            __syncthreads();
        }
        float fb[8];
        #pragma unroll
        for (int j = 0; j < 8; j++) fb[j] = __ldg(&Fb[tc + 32*j]);
        #pragma unroll
        for (int i = 0; i < 8; i++)
            #pragma unroll
            for (int j = 0; j < 8; j++)
                s_bm[(tr + 8*i)*257 + tc + 32*j] = fmaxf(acc[i][j] + fb[j], 0.f);
    }
    __syncthreads();

    // ---- P3: e[s][z] = sum_f a_m[b,s,f] * b_m[z,f]  (128x64, K=256) ----
    {
        const int tr = tid >> 3, tc = tid & 7;   // tr: s-groups, tc: z-groups
        float acc[4][8];
        #pragma unroll
        for (int i = 0; i < 4; i++)
            #pragma unroll
            for (int j = 0; j < 8; j++) acc[i][j] = 0.f;
        float* ast = s_buf;                      // [128][17]
        const float* amp = g_am + b*NS*ND;
        for (int k0 = 0; k0 < ND; k0 += 16) {
            #pragma unroll
            for (int t = 0; t < 8; t++) {
                int idx2 = tid + 256*t;
                int s = idx2 >> 4, kk = idx2 & 15;
                ast[s*17 + kk] = amp[s*ND + k0 + kk];
            }
            __syncthreads();
            #pragma unroll
            for (int kk = 0; kk < 16; kk++) {
                float av[4], bv[8];
                #pragma unroll
                for (int i = 0; i < 4; i++) av[i] = ast[(tr + 32*i)*17 + kk];
                #pragma unroll
                for (int j = 0; j < 8; j++) bv[j] = s_bm[(tc + 8*j)*257 + k0 + kk];
                #pragma unroll
                for (int i = 0; i < 4; i++)
                    #pragma unroll
                    for (int j = 0; j < 8; j++) acc[i][j] += av[i]*bv[j];
            }
            __syncthreads();
        }
        #pragma unroll
        for (int i = 0; i < 4; i++)
            #pragma unroll
            for (int j = 0; j < 8; j++)
                s_e[(tr + 32*i)*65 + tc + 8*j] = acc[i][j];
    }
    __syncthreads();

    // ---- P4a: beta = softmax over z (rows of e) -> s_beta ----
    {
        const int warp = tid >> 5, lane = tid & 31;
        for (int r = 0; r < 16; r++) {
            int s = warp*16 + r;
            float v0 = s_e[s*65 + lane];
            float v1 = s_e[s*65 + lane + 32];
            float mx = fmaxf(v0, v1);
            #pragma unroll
            for (int off = 16; off >= 1; off >>= 1)
                mx = fmaxf(mx, __shfl_xor_sync(0xffffffffu, mx, off));
            float e0 = expf(v0 - mx), e1 = expf(v1 - mx);
            float ss = e0 + e1;
            #pragma unroll
            for (int off = 16; off >= 1; off >>= 1)
                ss += __shfl_xor_sync(0xffffffffu, ss, off);
            float inv = 1.f / ss;
            s_beta[s*65 + lane]      = e0 * inv;
            s_beta[s*65 + lane + 32] = e1 * inv;
        }
    }
    __syncthreads();

    // ---- P4b: alpha = softmax over s (cols of e), in place ----
    {
        const int z = tid >> 2, q = tid & 3;     // 4 threads per column
        float mx = -1e30f;
        float ev[32];
        #pragma unroll
        for (int i = 0; i < 32; i++) {
            ev[i] = s_e[(q*32 + i)*65 + z];
            mx = fmaxf(mx, ev[i]);
        }
        mx = fmaxf(mx, __shfl_xor_sync(0xffffffffu, mx, 1));
        mx = fmaxf(mx, __shfl_xor_sync(0xffffffffu, mx, 2));
        float ss = 0.f;
        #pragma unroll
        for (int i = 0; i < 32; i++) { ev[i] = expf(ev[i] - mx); ss += ev[i]; }
        ss += __shfl_xor_sync(0xffffffffu, ss, 1);
        ss += __shfl_xor_sync(0xffffffffu, ss, 2);
        float inv = 1.f / ss;
        #pragma unroll
        for (int i = 0; i < 32; i++)
            s_e[(q*32 + i)*65 + z] = ev[i] * inv;
    }
    __syncthreads();

    // ---- P5: bbG2 = bb @ GW2  (64x256, K=256) -> s_buf ----
    {
        const int tr = tid >> 5, tc = tid & 31;
        float acc[8][8];
        #pragma unroll
        for (int i = 0; i < 8; i++)
            #pragma unroll
            for (int j = 0; j < 8; j++) acc[i][j] = 0.f;
        for (int k0 = 0; k0 < ND; k0 += 16) {
            #pragma unroll
            for (int t = 0; t < 16; t++)
                s_st5[t*256 + tid] = __ldg(&GW[(256 + k0 + t)*256 + tid]);
            __syncthreads();
            #pragma unroll
            for (int kk = 0; kk < 16; kk++) {
                float bv[8], wv[8];
                #pragma unroll
                for (int i = 0; i < 8; i++) bv[i] = s_bb[(tr + 8*i)*257 + k0 + kk];
                #pragma unroll
                for (int j = 0; j < 8; j++) wv[j] = s_st5[kk*256 + tc + 32*j];
                #pragma unroll
                for (int i = 0; i < 8; i++)
                    #pragma unroll
                    for (int j = 0; j < 8; j++) acc[i][j] += bv[i]*wv[j];
            }
            __syncthreads();
        }
        #pragma unroll
        for (int i = 0; i < 8; i++)
            #pragma unroll
            for (int j = 0; j < 8; j++)
                s_buf[(tr + 8*i)*256 + tc + 32*j] = acc[i][j];
    }
    __syncthreads();

    float y_local = 0.f;

    // ---- P6: y1 += sum_{s,g} relu(aG1[b,s,g] + (beta @ bbG2)[s,g]) * HW1[g] ----
    {
        const int tr = tid >> 4, tc = tid & 15;   // tr: s-groups (16), tc: g-groups (16)
        const float* aG1p = g_aG1 + b*NS*ND;
        for (int gb2 = 0; gb2 < 256; gb2 += 128) {
            float acc[8][8];
            #pragma unroll
            for (int i = 0; i < 8; i++)
                #pragma unroll
                for (int j = 0; j < 8; j++) acc[i][j] = 0.f;
            #pragma unroll 4
            for (int z = 0; z < NZ; z++) {
                float bv[8], wv[8];
                #pragma unroll
                for (int i = 0; i < 8; i++) bv[i] = s_beta[(tr + 16*i)*65 + z];
                #pragma unroll
                for (int j = 0; j < 8; j++) wv[j] = s_buf[z*256 + gb2 + tc + 16*j];
                #pragma unroll
                for (int i = 0; i < 8; i++)
                    #pragma unroll
                    for (int j = 0; j < 8; j++) acc[i][j] += bv[i]*wv[j];
            }
            #pragma unroll
            for (int j = 0; j < 8; j++) {
                int g = gb2 + tc + 16*j;
                float hw = __ldg(&HW[g]);
                #pragma unroll
                for (int i = 0; i < 8; i++) {
                    int s = tr + 16*i;
                    float v = acc[i][j] + __ldg(&aG1p[s*ND + g]);
                    y_local += fmaxf(v, 0.f) * hw;
                }
            }
        }
    }
    __syncthreads();

    // ---- P7: y2 += sum_{z,g} relu(bb@GW1 + Gb + alpha^T @ aG2) * HW2[g] ----
    {
        const int tr = tid >> 5, tc = tid & 31;   // tr: z-groups (8), tc: g-groups (32)
        float acc[8][8];
        #pragma unroll
        for (int j = 0; j < 8; j++) {
            float gb = __ldg(&Gb[tc + 32*j]);
            #pragma unroll
            for (int i = 0; i < 8; i++) acc[i][j] = gb;
        }
        float* wst = s_buf;   // bbG2 dead after P6
        // part 1: bb @ GW1 (K = 256)
        for (int k0 = 0; k0 < ND; k0 += 16) {
            #pragma unroll
            for (int t = 0; t < 16; t++)
                wst[t*256 + tid] = __ldg(&GW[(k0 + t)*256 + tid]);
            __syncthreads();
            #pragma unroll
            for (int kk = 0; kk < 16; kk++) {
                float bv[8], wv[8];
                #pragma unroll
                for (int i = 0; i < 8; i++) bv[i] = s_bb[(tr + 8*i)*257 + k0 + kk];
                #pragma unroll
                for (int j = 0; j < 8; j++) wv[j] = wst[kk*256 + tc + 32*j];
                #pragma unroll
                for (int i = 0; i < 8; i++)
                    #pragma unroll
                    for (int j = 0; j < 8; j++) acc[i][j] += bv[i]*wv[j];
            }
            __syncthreads();
        }
        // part 2: alpha^T @ aG2 (K = 128 over s)
        const float* aG2p = g_aG2 + b*NS*ND;
        for (int k0 = 0; k0 < NS; k0 += 16) {
            #pragma unroll
            for (int t = 0; t < 16; t++)
                wst[t*256 + tid] = aG2p[(k0 + t)*ND + tid];
            __syncthreads();
            #pragma unroll
            for (int kk = 0; kk < 16; kk++) {
                float av[8], wv[8];
                #pragma unroll
                for (int i = 0; i < 8; i++) av[i] = s_e[(k0 + kk)*65 + tr + 8*i];
                #pragma unroll
                for (int j = 0; j < 8; j++) wv[j] = wst[kk*256 + tc + 32*j];
                #pragma unroll
                for (int i = 0; i < 8; i++)
                    #pragma unroll
                    for (int j = 0; j < 8; j++) acc[i][j] += av[i]*wv[j];
            }
            __syncthreads();
        }
        #pragma unroll
        for (int j = 0; j < 8; j++) {
            float hw = __ldg(&HW[256 + tc + 32*j]);
            #pragma unroll
            for (int i = 0; i < 8; i++)
                y_local += fmaxf(acc[i][j], 0.f) * hw;
        }
    }
    __syncthreads();

    // ---- block reduce y_local -> out[p] ----
    {
        const int warp = tid >> 5, lane = tid & 31;
        #pragma unroll
        for (int off = 16; off >= 1; off >>= 1)
            y_local += __shfl_xor_sync(0xffffffffu, y_local, off);
        float* red = s_e;   // reuse
        if (lane == 0) red[warp] = y_local;
        __syncthreads();
        if (tid == 0) {
            float t = 0.f;
            #pragma unroll
            for (int w = 0; w < 8; w++) t += red[w];
            out[p] = t + __ldg(&Hb[0]);
        }
    }
}

// =========================================================================
extern "C" void kernel_launch(void* const* d_in, const int* in_sizes, int n_in,
                              void* d_out, int out_size)
{
    const int*   inptensor = (const int*)  d_in[0];
    const int*   cand      = (const int*)  d_in[1];
    // d_in[2] alignments, d_in[3] align_entropies: unused by the model
    const float* EmbA      = (const float*)d_in[4];
    const float* EmbB      = (const float*)d_in[5];
    const float* FW        = (const float*)d_in[6];
    const float* Fb        = (const float*)d_in[7];
    const float* GW        = (const float*)d_in[8];
    const float* Gb        = (const float*)d_in[9];
    const float* HW        = (const float*)d_in[10];
    const float* Hb        = (const float*)d_in[11];
    float*       out       = (float*)d_out;

    (void)in_sizes; (void)n_in; (void)out_size;

    const int smem1 = (128*257 + 16*64) * 4;          // 135680 B
    const int smem2 = 57600 * 4;                      // 230400 B
    cudaFuncSetAttribute(stage1_kernel, cudaFuncAttributeMaxDynamicSharedMemorySize, smem1);
    cudaFuncSetAttribute(pair_kernel,   cudaFuncAttributeMaxDynamicSharedMemorySize, smem2);

    stage1_kernel<<<dim3(12, 32), 256, smem1>>>(inptensor, EmbA, FW, Fb, GW, Gb);
    pair_kernel<<<NB*NC, 256, smem2>>>(cand, EmbB, FW, Fb, GW, Gb, HW, Hb, out);
}

// round 3
// speedup vs baseline: 1.8737x; 1.8737x over previous
#include <cuda_runtime.h>
#include <cstdint>

#define NB 32
#define NC 64
#define NS 128
#define NZ 64
#define ND 256

// smem region offsets (in floats)
#define PBB   260   // bb pitch        (A-role)
#define PBM   260   // b_m pitch
#define PE    72    // e/alpha pitch
#define PBETA 68    // beta pitch
#define PW    264   // weight/bbG2 pitch (B-role)
#define PAM   20    // a_m k-tile pitch

#define OFF_BB    0
#define OFF_BETA  16640
#define OFF_STG   16640
#define OFF_STG5  25344
#define OFF_E     29568
#define OFF_R4    38784
#define OFF_HW    55680
#define OFF_GB    56192
#define OFF_FB    56448
#define OFF_RED   56704
#define SMEM_FL   56720
#define STG_BUF   4224   // [16][264]

// ---------------- device scratch ----------------
__device__ float g_am [NB*NS*ND];   // relu(a@FW + Fb)
__device__ float g_aG1[NB*NS*ND];   // a@GW1 + Gb
__device__ float g_aG2[NB*NS*ND];   // a@GW2

// ---------------- tf32 mma helpers ----------------
__device__ __forceinline__ uint32_t f2t(float f){
    uint32_t u; asm("cvt.rna.tf32.f32 %0, %1;" : "=r"(u) : "f"(f)); return u;
}
// A-fragment register order (PTX ISA m16n8k8.tf32):
//   a0=(r,c)  a1=(r+8,c)  a2=(r,c+4)  a3=(r+8,c+4)
__device__ __forceinline__ void mma8(float* d,
    uint32_t a0,uint32_t a1,uint32_t a2,uint32_t a3, uint32_t b0,uint32_t b1){
    asm volatile("mma.sync.aligned.m16n8k8.row.col.f32.tf32.tf32.f32 "
        "{%0,%1,%2,%3}, {%4,%5,%6,%7}, {%8,%9}, {%0,%1,%2,%3};\n"
        : "+f"(d[0]),"+f"(d[1]),"+f"(d[2]),"+f"(d[3])
        : "r"(a0),"r"(a1),"r"(a2),"r"(a3),"r"(b0),"r"(b1));
}

// stage a [16][256] row-major gmem tile into smem [16][264]
__device__ __forceinline__ void stage_w(const float* __restrict__ g, float* s,
                                        int k0, int tid){
    int kk = tid >> 4;
    int c4 = (tid & 15) * 16;
    const float4* gp = (const float4*)(g + (size_t)(k0+kk)*256 + c4);
    float4 v0 = __ldg(gp+0), v1 = __ldg(gp+1), v2 = __ldg(gp+2), v3 = __ldg(gp+3);
    float* sp = s + kk*PW + c4;
    *(float4*)(sp+0)=v0; *(float4*)(sp+4)=v1; *(float4*)(sp+8)=v2; *(float4*)(sp+12)=v3;
}

// stage a_m k-tile: [128 rows][16 k] into smem [128][20]
__device__ __forceinline__ void stage_am(const float* __restrict__ g, float* s,
                                         int k0, int tid){
    int srow = tid >> 1;
    int kc = (tid & 1) * 8;
    const float4* gp = (const float4*)(g + (size_t)srow*ND + k0 + kc);
    float4 v0 = __ldg(gp), v1 = __ldg(gp+1);
    float* sp = s + srow*PAM + kc;
    *(float4*)(sp) = v0; *(float4*)(sp+4) = v1;
}

// =========================================================================
// Stage 1 (fp32 FFMA, exact): a_m / aG1 / aG2.  grid (12, 32), 256 thr.
// =========================================================================
__global__ void __launch_bounds__(256) stage1_kernel(
    const int*   __restrict__ inptensor,
    const float* __restrict__ EmbA,
    const float* __restrict__ FW,
    const float* __restrict__ Fb,
    const float* __restrict__ GW,
    const float* __restrict__ Gb)
{
    extern __shared__ float sm[];
    float* a_tile = sm;              // 128*257
    float* wst    = sm + 128*257;    // 16*64

    const int b     = blockIdx.y;
    const int chunk = blockIdx.x;
    const int m     = chunk >> 2;
    const int gbase = (chunk & 3) * 64;
    const int tid   = threadIdx.x;

    for (int s = 0; s < NS; s++) {
        int idx = __ldg(&inptensor[b*NS + s]);
        a_tile[s*257 + tid] = __ldg(&EmbA[(size_t)idx*ND + tid]);
    }
    __syncthreads();

    const int tr = tid >> 3;
    const int tc = tid & 7;

    float acc[4][8];
    #pragma unroll
    for (int i = 0; i < 4; i++)
        #pragma unroll
        for (int j = 0; j < 8; j++) acc[i][j] = 0.f;

    for (int k0 = 0; k0 < ND; k0 += 16) {
        #pragma unroll
        for (int t = 0; t < 4; t++) {
            int idx2 = tid + 256*t;
            int kk = idx2 >> 6, gg = idx2 & 63;
            int row = k0 + kk + (m == 2 ? 256 : 0);
            const float* Wsrc = (m == 0) ? FW : GW;
            wst[idx2] = __ldg(&Wsrc[row*256 + gbase + gg]);
        }
        __syncthreads();
        #pragma unroll
        for (int kk = 0; kk < 16; kk++) {
            float av[4], wv[8];
            #pragma unroll
            for (int i = 0; i < 4; i++) av[i] = a_tile[(tr + 32*i)*257 + k0 + kk];
            #pragma unroll
            for (int j = 0; j < 8; j++) wv[j] = wst[kk*64 + tc + 8*j];
            #pragma unroll
            for (int i = 0; i < 4; i++)
                #pragma unroll
                for (int j = 0; j < 8; j++) acc[i][j] += av[i]*wv[j];
        }
        __syncthreads();
    }

    float* outp = (m == 0) ? g_am : (m == 1 ? g_aG1 : g_aG2);
    #pragma unroll
    for (int j = 0; j < 8; j++) {
        int g = gbase + tc + 8*j;
        float bias = (m == 0) ? __ldg(&Fb[g]) : (m == 1 ? __ldg(&Gb[g]) : 0.f);
        #pragma unroll
        for (int i = 0; i < 4; i++) {
            float v = acc[i][j] + bias;
            if (m == 0) v = fmaxf(v, 0.f);
            outp[(size_t)(b*NS + tr + 32*i)*ND + g] = v;
        }
    }
}

// =========================================================================
// Stage 2: one CTA per (b,c). 256 threads. tf32 tensor-core phases.
// =========================================================================
__global__ void __launch_bounds__(256) pair_kernel(
    const int*   __restrict__ cand,
    const float* __restrict__ EmbB,
    const float* __restrict__ FW,
    const float* __restrict__ Fb,
    const float* __restrict__ GW,
    const float* __restrict__ Gb,
    const float* __restrict__ HW,
    const float* __restrict__ Hb,
    float*       __restrict__ out)
{
    extern __shared__ float sm[];
    float* s_bb   = sm + OFF_BB;     // [64][260]
    float* s_bm   = sm + OFF_R4;     // [64][260]  (R4: later bbG2)
    float* s_bbG2 = sm + OFF_R4;     // [64][264]
    float* s_e    = sm + OFF_E;      // [128][72]
    float* s_beta = sm + OFF_BETA;   // [128][68]
    float* sHW    = sm + OFF_HW;
    float* sGb    = sm + OFF_GB;
    float* sFb    = sm + OFF_FB;
    float* sRed   = sm + OFF_RED;

    const int tid  = threadIdx.x;
    const int p    = blockIdx.x;
    const int b    = p >> 6;
    const int w    = tid >> 5;
    const int lane = tid & 31;
    const int r    = lane >> 2;
    const int c    = lane & 3;

    // ---- P0: preload biases / HW ----
    sHW[tid] = __ldg(&HW[tid]);
    sHW[tid + 256] = __ldg(&HW[tid + 256]);
    sGb[tid] = __ldg(&Gb[tid]);
    sFb[tid] = __ldg(&Fb[tid]);

    // ---- P1: gather bb = EmbB[cand[b,c,:]] ----
    {
        const int* ci = cand + p*NZ;
        for (int z = 0; z < NZ; z++) {
            int idx = __ldg(&ci[z]);
            s_bb[z*PBB + tid] = __ldg(&EmbB[(size_t)idx*ND + tid]);
        }
    }
    __syncthreads();

    // ---- P2: b_m = relu(bb @ FW + Fb) -> s_bm (R4) ----
    {
        const int wm = w >> 2;      // 0..1
        const int wn = w & 3;       // 0..3
        float acc[2][8][4];
        #pragma unroll
        for (int mi=0;mi<2;mi++)
            #pragma unroll
            for (int f=0;f<8;f++)
                #pragma unroll
                for (int e=0;e<4;e++) acc[mi][f][e]=0.f;

        stage_w(FW, sm + OFF_STG, 0, tid);
        __syncthreads();
        for (int t = 0; t < 16; t++){
            const float* cw = sm + OFF_STG + (t&1)*STG_BUF;
            if (t < 15) stage_w(FW, sm + OFF_STG + ((t+1)&1)*STG_BUF, (t+1)*16, tid);
            #pragma unroll
            for (int kh = 0; kh < 2; kh++){
                int kg = t*16 + kh*8;
                int kl = kh*8;
                uint32_t afr[2][4];
                #pragma unroll
                for (int mi = 0; mi < 2; mi++){
                    const float* ap = s_bb + (wm*32 + mi*16 + r)*PBB + kg + c;
                    afr[mi][0]=f2t(ap[0]);        afr[mi][1]=f2t(ap[8*PBB]);
                    afr[mi][2]=f2t(ap[4]);        afr[mi][3]=f2t(ap[8*PBB+4]);
                }
                #pragma unroll
                for (int f = 0; f < 8; f++){
                    const float* bp = cw + (kl + c)*PW + wn*64 + f*8 + r;
                    uint32_t b0 = f2t(bp[0]);
                    uint32_t b1 = f2t(bp[4*PW]);
                    mma8(acc[0][f], afr[0][0],afr[0][1],afr[0][2],afr[0][3], b0,b1);
                    mma8(acc[1][f], afr[1][0],afr[1][1],afr[1][2],afr[1][3], b0,b1);
                }
            }
            __syncthreads();
        }
        #pragma unroll
        for (int mi=0;mi<2;mi++)
            #pragma unroll
            for (int f=0;f<8;f++){
                int row0 = wm*32 + mi*16 + r;
                int col0 = wn*64 + f*8 + c*2;
                float fb0 = sFb[col0], fb1 = sFb[col0+1];
                s_bm[row0*PBM + col0]       = fmaxf(acc[mi][f][0] + fb0, 0.f);
                s_bm[row0*PBM + col0+1]     = fmaxf(acc[mi][f][1] + fb1, 0.f);
                s_bm[(row0+8)*PBM + col0]   = fmaxf(acc[mi][f][2] + fb0, 0.f);
                s_bm[(row0+8)*PBM + col0+1] = fmaxf(acc[mi][f][3] + fb1, 0.f);
            }
    }
    __syncthreads();

    // ---- P3: e[s][z] = a_m @ b_m^T -> s_e ----
    {
        const int wm = w >> 1;      // 0..3
        const int wn = w & 1;       // 0..1
        float acc[2][4][4];
        #pragma unroll
        for (int mi=0;mi<2;mi++)
            #pragma unroll
            for (int f=0;f<4;f++)
                #pragma unroll
                for (int e=0;e<4;e++) acc[mi][f][e]=0.f;

        const float* amg = g_am + (size_t)b*NS*ND;
        stage_am(amg, sm + OFF_STG, 0, tid);
        __syncthreads();
        for (int t = 0; t < 16; t++){
            const float* ca = sm + OFF_STG + (t&1)*STG_BUF;
            if (t < 15) stage_am(amg, sm + OFF_STG + ((t+1)&1)*STG_BUF, (t+1)*16, tid);
            #pragma unroll
            for (int kh = 0; kh < 2; kh++){
                int kg = t*16 + kh*8;
                int kl = kh*8;
                uint32_t afr[2][4];
                #pragma unroll
                for (int mi = 0; mi < 2; mi++){
                    const float* ap = ca + (wm*32 + mi*16 + r)*PAM + kl + c;
                    afr[mi][0]=f2t(ap[0]);        afr[mi][1]=f2t(ap[8*PAM]);
                    afr[mi][2]=f2t(ap[4]);        afr[mi][3]=f2t(ap[8*PAM+4]);
                }
                #pragma unroll
                for (int f = 0; f < 4; f++){
                    const float* bp = s_bm + (wn*32 + f*8 + r)*PBM + kg + c;
                    uint32_t b0 = f2t(bp[0]);
                    uint32_t b1 = f2t(bp[4]);
                    mma8(acc[0][f], afr[0][0],afr[0][1],afr[0][2],afr[0][3], b0,b1);
                    mma8(acc[1][f], afr[1][0],afr[1][1],afr[1][2],afr[1][3], b0,b1);
                }
            }
            __syncthreads();
        }
        #pragma unroll
        for (int mi=0;mi<2;mi++)
            #pragma unroll
            for (int f=0;f<4;f++){
                int row0 = wm*32 + mi*16 + r;
                int col0 = wn*32 + f*8 + c*2;
                s_e[row0*PE + col0]       = acc[mi][f][0];
                s_e[row0*PE + col0+1]     = acc[mi][f][1];
                s_e[(row0+8)*PE + col0]   = acc[mi][f][2];
                s_e[(row0+8)*PE + col0+1] = acc[mi][f][3];
            }
    }
    __syncthreads();

    // ---- P4a: beta = softmax over z (rows) -> s_beta ----
    {
        for (int rr = 0; rr < 16; rr++) {
            int s = w*16 + rr;
            float v0 = s_e[s*PE + lane];
            float v1 = s_e[s*PE + lane + 32];
            float mx = fmaxf(v0, v1);
            #pragma unroll
            for (int off = 16; off >= 1; off >>= 1)
                mx = fmaxf(mx, __shfl_xor_sync(0xffffffffu, mx, off));
            float e0 = expf(v0 - mx), e1 = expf(v1 - mx);
            float ss = e0 + e1;
            #pragma unroll
            for (int off = 16; off >= 1; off >>= 1)
                ss += __shfl_xor_sync(0xffffffffu, ss, off);
            float inv = 1.f / ss;
            s_beta[s*PBETA + lane]      = e0 * inv;
            s_beta[s*PBETA + lane + 32] = e1 * inv;
        }
    }
    __syncthreads();

    // ---- P4b: alpha = softmax over s (cols), in place on s_e ----
    {
        const int z = tid >> 2, q = tid & 3;
        float mx = -1e30f;
        float ev[32];
        #pragma unroll
        for (int i = 0; i < 32; i++) {
            ev[i] = s_e[(q*32 + i)*PE + z];
            mx = fmaxf(mx, ev[i]);
        }
        mx = fmaxf(mx, __shfl_xor_sync(0xffffffffu, mx, 1));
        mx = fmaxf(mx, __shfl_xor_sync(0xffffffffu, mx, 2));
        float ss = 0.f;
        #pragma unroll
        for (int i = 0; i < 32; i++) { ev[i] = expf(ev[i] - mx); ss += ev[i]; }
        ss += __shfl_xor_sync(0xffffffffu, ss, 1);
        ss += __shfl_xor_sync(0xffffffffu, ss, 2);
        float inv = 1.f / ss;
        #pragma unroll
        for (int i = 0; i < 32; i++)
            s_e[(q*32 + i)*PE + z] = ev[i] * inv;
    }
    __syncthreads();

    // ---- P5: bbG2 = bb @ GW2 -> s_bbG2 (R4), single-buffered staging ----
    {
        const int wm = w >> 2;
        const int wn = w & 3;
        float acc[2][8][4];
        #pragma unroll
        for (int mi=0;mi<2;mi++)
            #pragma unroll
            for (int f=0;f<8;f++)
                #pragma unroll
                for (int e=0;e<4;e++) acc[mi][f][e]=0.f;

        const float* GW2 = GW + 256*256;
        float* stg = sm + OFF_STG5;
        for (int t = 0; t < 16; t++){
            stage_w(GW2, stg, t*16, tid);
            __syncthreads();
            #pragma unroll
            for (int kh = 0; kh < 2; kh++){
                int kg = t*16 + kh*8;
                int kl = kh*8;
                uint32_t afr[2][4];
                #pragma unroll
                for (int mi = 0; mi < 2; mi++){
                    const float* ap = s_bb + (wm*32 + mi*16 + r)*PBB + kg + c;
                    afr[mi][0]=f2t(ap[0]);        afr[mi][1]=f2t(ap[8*PBB]);
                    afr[mi][2]=f2t(ap[4]);        afr[mi][3]=f2t(ap[8*PBB+4]);
                }
                #pragma unroll
                for (int f = 0; f < 8; f++){
                    const float* bp = stg + (kl + c)*PW + wn*64 + f*8 + r;
                    uint32_t b0 = f2t(bp[0]);
                    uint32_t b1 = f2t(bp[4*PW]);
                    mma8(acc[0][f], afr[0][0],afr[0][1],afr[0][2],afr[0][3], b0,b1);
                    mma8(acc[1][f], afr[1][0],afr[1][1],afr[1][2],afr[1][3], b0,b1);
                }
            }
            __syncthreads();
        }
        #pragma unroll
        for (int mi=0;mi<2;mi++)
            #pragma unroll
            for (int f=0;f<8;f++){
                int row0 = wm*32 + mi*16 + r;
                int col0 = wn*64 + f*8 + c*2;
                s_bbG2[row0*PW + col0]       = acc[mi][f][0];
                s_bbG2[row0*PW + col0+1]     = acc[mi][f][1];
                s_bbG2[(row0+8)*PW + col0]   = acc[mi][f][2];
                s_bbG2[(row0+8)*PW + col0+1] = acc[mi][f][3];
            }
    }
    __syncthreads();

    float y_local = 0.f;

    // ---- P6: y1 += sum relu(aG1 + beta @ bbG2) * HW1 ----
    {
        const int wm = w >> 1;      // 0..3
        const int wn = w & 1;       // 0..1
        const float* aG1p = g_aG1 + (size_t)b*NS*ND;
        #pragma unroll
        for (int pass = 0; pass < 2; pass++){
            int nb = wn*128 + pass*64;
            float acc[2][8][4];
            #pragma unroll
            for (int mi=0;mi<2;mi++)
                #pragma unroll
                for (int f=0;f<8;f++)
                    #pragma unroll
                    for (int e=0;e<4;e++) acc[mi][f][e]=0.f;
            #pragma unroll
            for (int k8 = 0; k8 < 8; k8++){
                int k0 = k8*8;
                uint32_t afr[2][4];
                #pragma unroll
                for (int mi = 0; mi < 2; mi++){
                    const float* ap = s_beta + (wm*32 + mi*16 + r)*PBETA + k0 + c;
                    afr[mi][0]=f2t(ap[0]);        afr[mi][1]=f2t(ap[8*PBETA]);
                    afr[mi][2]=f2t(ap[4]);        afr[mi][3]=f2t(ap[8*PBETA+4]);
                }
                #pragma unroll
                for (int f = 0; f < 8; f++){
                    const float* bp = s_bbG2 + (k0 + c)*PW + nb + f*8 + r;
                    uint32_t b0 = f2t(bp[0]);
                    uint32_t b1 = f2t(bp[4*PW]);
                    mma8(acc[0][f], afr[0][0],afr[0][1],afr[0][2],afr[0][3], b0,b1);
                    mma8(acc[1][f], afr[1][0],afr[1][1],afr[1][2],afr[1][3], b0,b1);
                }
            }
            #pragma unroll
            for (int mi=0;mi<2;mi++)
                #pragma unroll
                for (int f=0;f<8;f++){
                    int row0 = wm*32 + mi*16 + r;
                    int col0 = nb + f*8 + c*2;
                    float2 g0 = __ldg((const float2*)(aG1p + (size_t)row0*ND + col0));
                    float2 g1 = __ldg((const float2*)(aG1p + (size_t)(row0+8)*ND + col0));
                    float h0 = sHW[col0], h1 = sHW[col0+1];
                    y_local += fmaxf(acc[mi][f][0] + g0.x, 0.f)*h0
                             + fmaxf(acc[mi][f][1] + g0.y, 0.f)*h1
                             + fmaxf(acc[mi][f][2] + g1.x, 0.f)*h0
                             + fmaxf(acc[mi][f][3] + g1.y, 0.f)*h1;
                }
        }
    }
    __syncthreads();

    // ---- P7: y2 += sum relu(bb@GW1 + Gb + alpha^T @ aG2) * HW2 ----
    {
        const int wm = w >> 2;      // 0..1 -> z block
        const int wn = w & 3;       // 0..3 -> g block
        float acc[2][8][4];
        #pragma unroll
        for (int f=0;f<8;f++){
            int col0 = wn*64 + f*8 + c*2;
            float gb0 = sGb[col0], gb1 = sGb[col0+1];
            #pragma unroll
            for (int mi=0;mi<2;mi++){
                acc[mi][f][0]=gb0; acc[mi][f][1]=gb1; acc[mi][f][2]=gb0; acc[mi][f][3]=gb1;
            }
        }
        // part 1: bb @ GW1 (K=256)
        stage_w(GW, sm + OFF_STG, 0, tid);
        __syncthreads();
        for (int t = 0; t < 16; t++){
            const float* cw = sm + OFF_STG + (t&1)*STG_BUF;
            if (t < 15) stage_w(GW, sm + OFF_STG + ((t+1)&1)*STG_BUF, (t+1)*16, tid);
            #pragma unroll
            for (int kh = 0; kh < 2; kh++){
                int kg = t*16 + kh*8;
                int kl = kh*8;
                uint32_t afr[2][4];
                #pragma unroll
                for (int mi = 0; mi < 2; mi++){
                    const float* ap = s_bb + (wm*32 + mi*16 + r)*PBB + kg + c;
                    afr[mi][0]=f2t(ap[0]);        afr[mi][1]=f2t(ap[8*PBB]);
                    afr[mi][2]=f2t(ap[4]);        afr[mi][3]=f2t(ap[8*PBB+4]);
                }
                #pragma unroll
                for (int f = 0; f < 8; f++){
                    const float* bp = cw + (kl + c)*PW + wn*64 + f*8 + r;
                    uint32_t b0 = f2t(bp[0]);
                    uint32_t b1 = f2t(bp[4*PW]);
                    mma8(acc[0][f], afr[0][0],afr[0][1],afr[0][2],afr[0][3], b0,b1);
                    mma8(acc[1][f], afr[1][0],afr[1][1],afr[1][2],afr[1][3], b0,b1);
                }
            }
            __syncthreads();
        }
        // part 2: alpha^T @ aG2 (K=128 over s)
        const float* aG2g = g_aG2 + (size_t)b*NS*ND;
        stage_w(aG2g, sm + OFF_STG, 0, tid);
        __syncthreads();
        for (int t = 0; t < 8; t++){
            const float* cw = sm + OFF_STG + (t&1)*STG_BUF;
            if (t < 7) stage_w(aG2g, sm + OFF_STG + ((t+1)&1)*STG_BUF, (t+1)*16, tid);
            #pragma unroll
            for (int kh = 0; kh < 2; kh++){
                int kg = t*16 + kh*8;   // global s
                int kl = kh*8;
                uint32_t afr[2][4];
                #pragma unroll
                for (int mi = 0; mi < 2; mi++){
                    int m0 = wm*32 + mi*16;
                    const float* ap = s_e + (kg + c)*PE + m0 + r;
                    afr[mi][0]=f2t(ap[0]);
                    afr[mi][1]=f2t(ap[8]);
                    afr[mi][2]=f2t(ap[4*PE]);
                    afr[mi][3]=f2t(ap[4*PE+8]);
                }
                #pragma unroll
                for (int f = 0; f < 8; f++){
                    const float* bp = cw + (kl + c)*PW + wn*64 + f*8 + r;
                    uint32_t b0 = f2t(bp[0]);
                    uint32_t b1 = f2t(bp[4*PW]);
                    mma8(acc[0][f], afr[0][0],afr[0][1],afr[0][2],afr[0][3], b0,b1);
                    mma8(acc[1][f], afr[1][0],afr[1][1],afr[1][2],afr[1][3], b0,b1);
                }
            }
            __syncthreads();
        }
        #pragma unroll
        for (int mi=0;mi<2;mi++)
            #pragma unroll
            for (int f=0;f<8;f++){
                int col0 = wn*64 + f*8 + c*2;
                float h0 = sHW[256+col0], h1 = sHW[256+col0+1];
                y_local += fmaxf(acc[mi][f][0], 0.f)*h0
                         + fmaxf(acc[mi][f][1], 0.f)*h1
                         + fmaxf(acc[mi][f][2], 0.f)*h0
                         + fmaxf(acc[mi][f][3], 0.f)*h1;
            }
    }
    __syncthreads();

    // ---- block reduce ----
    {
        #pragma unroll
        for (int off = 16; off >= 1; off >>= 1)
            y_local += __shfl_xor_sync(0xffffffffu, y_local, off);
        if (lane == 0) sRed[w] = y_local;
        __syncthreads();
        if (tid == 0) {
            float t = 0.f;
            #pragma unroll
            for (int ww = 0; ww < 8; ww++) t += sRed[ww];
            out[p] = t + __ldg(&Hb[0]);
        }
    }
}

// =========================================================================
extern "C" void kernel_launch(void* const* d_in, const int* in_sizes, int n_in,
                              void* d_out, int out_size)
{
    const int*   inptensor = (const int*)  d_in[0];
    const int*   cand      = (const int*)  d_in[1];
    const float* EmbA      = (const float*)d_in[4];
    const float* EmbB      = (const float*)d_in[5];
    const float* FW        = (const float*)d_in[6];
    const float* Fb        = (const float*)d_in[7];
    const float* GW        = (const float*)d_in[8];
    const float* Gb        = (const float*)d_in[9];
    const float* HW        = (const float*)d_in[10];
    const float* Hb        = (const float*)d_in[11];
    float*       out       = (float*)d_out;

    (void)in_sizes; (void)n_in; (void)out_size;

    const int smem1 = (128*257 + 16*64) * 4;   // 135680 B
    const int smem2 = SMEM_FL * 4;             // 226880 B
    cudaFuncSetAttribute(stage1_kernel, cudaFuncAttributeMaxDynamicSharedMemorySize, smem1);
    cudaFuncSetAttribute(pair_kernel,   cudaFuncAttributeMaxDynamicSharedMemorySize, smem2);

    stage1_kernel<<<dim3(12, 32), 256, smem1>>>(inptensor, EmbA, FW, Fb, GW, Gb);
    pair_kernel<<<NB*NC, 256, smem2>>>(cand, EmbB, FW, Fb, GW, Gb, HW, Hb, out);
}

// round 4
// speedup vs baseline: 3.4773x; 1.8559x over previous
#include <cuda_runtime.h>
#include <cstdint>

#define NB 32
#define NC 64
#define NS 128
#define NZ 64
#define ND 256
#define VO 5000
#define VOP 5120

// pitches (floats) — all verified conflict-free for their fragment patterns
#define PBM   260   // b_m      (B-role in P3: (f*8+r)*260+c -> bank 4r+c)
#define PW    264   // bbG2 / staged aG2 (B-role: c*264+f*8+r -> bank 8c+8f+r)
#define PE    72    // e/alpha  (P7 A-role: c*72+r -> 8c+r)
#define PBETA 68    // beta     (P6 A-role: r*68+c -> 4r+c)
#define PAM   20    // a_m k-tiles (A-role: r*20+c -> unique mod 32)

// pair-kernel smem float offsets
#define OFF_BG2  0            // bbG2 [64][264] = 16896
#define OFF_BM   16896        // b_m  [64][260] = 16640 ; P7 staging reuses
#define OFF_STG7 16896        // aG2 staging [16][264] x2 = 8448
#define OFF_BETA 33536        // beta [128][68] = 8704 ; P3 am staging lives here first
#define OFF_STG3 33536        // am staging [128][20] x2 = 5120
#define OFF_E    42240        // e/alpha [128][72] = 9216
#define OFF_CID  51456        // 64 ints
#define OFF_HW   51520        // 512
#define OFF_RED  52032        // 8
#define SMEM_FL  52040
#define STG_BUF  4224         // 16*264
#define STG_AM   2560         // 128*20

// ---------------- device scratch ----------------
__device__ float g_am [NB*NS*ND];   // tf32-rounded relu(a@FW+Fb)
__device__ float g_aG1[NB*NS*ND];   // exact a@GW1 + Gb
__device__ float g_aG2[NB*NS*ND];   // tf32-rounded a@GW2
__device__ float g_bm [VOP*ND];     // tf32-rounded relu(EmbB@FW+Fb)
__device__ float g_bg1[VOP*ND];     // exact EmbB@GW1 + Gb
__device__ float g_bg2[VOP*ND];     // tf32-rounded EmbB@GW2

// ---------------- helpers ----------------
__device__ __forceinline__ uint32_t f2t(float f){
    uint32_t u; asm("cvt.rna.tf32.f32 %0, %1;" : "=r"(u) : "f"(f)); return u;
}
__device__ __forceinline__ float rtf(float f){ return __uint_as_float(f2t(f)); }
__device__ __forceinline__ uint32_t ldu(const float* p){ return __float_as_uint(*p); }

// A-fragment order (m16n8k8.tf32): a0=(r,c) a1=(r+8,c) a2=(r,c+4) a3=(r+8,c+4)
__device__ __forceinline__ void mma8(float* d,
    uint32_t a0,uint32_t a1,uint32_t a2,uint32_t a3, uint32_t b0,uint32_t b1){
    asm volatile("mma.sync.aligned.m16n8k8.row.col.f32.tf32.tf32.f32 "
        "{%0,%1,%2,%3}, {%4,%5,%6,%7}, {%8,%9}, {%0,%1,%2,%3};\n"
        : "+f"(d[0]),"+f"(d[1]),"+f"(d[2]),"+f"(d[3])
        : "r"(a0),"r"(a1),"r"(a2),"r"(a3),"r"(b0),"r"(b1));
}

// stage a [16][256] gmem tile (values already tf32-rounded) into smem [16][264]
__device__ __forceinline__ void stage_w(const float* __restrict__ g, float* s,
                                        int k0, int tid){
    int kk = tid >> 4;
    int c4 = (tid & 15) * 16;
    const float4* gp = (const float4*)(g + (size_t)(k0+kk)*256 + c4);
    float4 v0 = __ldg(gp+0), v1 = __ldg(gp+1), v2 = __ldg(gp+2), v3 = __ldg(gp+3);
    float* sp = s + kk*PW + c4;
    *(float4*)(sp+0)=v0; *(float4*)(sp+4)=v1; *(float4*)(sp+8)=v2; *(float4*)(sp+12)=v3;
}

// stage a_m k-tile: [128 rows][16 k] into smem [128][20]
__device__ __forceinline__ void stage_am(const float* __restrict__ g, float* s,
                                         int k0, int tid){
    int srow = tid >> 1;
    int kc = (tid & 1) * 8;
    const float4* gp = (const float4*)(g + (size_t)srow*ND + k0 + kc);
    float4 v0 = __ldg(gp), v1 = __ldg(gp+1);
    float* sp = s + srow*PAM + kc;
    *(float4*)(sp) = v0; *(float4*)(sp+4) = v1;
}

// =========================================================================
// Unified table kernel (exact fp32 FFMA).
// grid = (12, 72):  y<32 -> a-side (gathered per batch b=y);
//                   y>=32 -> b-side vocab tile rt=y-32 (128 rows of EmbB).
// chunk = blockIdx.x: m = chunk>>2 (0: F+relu, 1: GW1+Gb, 2: GW2), gchunk of 64.
// =========================================================================
__global__ void __launch_bounds__(256) tables_kernel(
    const int*   __restrict__ inptensor,
    const float* __restrict__ EmbA,
    const float* __restrict__ EmbB,
    const float* __restrict__ FW,
    const float* __restrict__ Fb,
    const float* __restrict__ GW,
    const float* __restrict__ Gb)
{
    extern __shared__ float sm[];
    float* a_tile = sm;              // 128*257
    float* wst    = sm + 128*257;    // 16*64

    const int y     = blockIdx.y;
    const int chunk = blockIdx.x;
    const int m     = chunk >> 2;
    const int gbase = (chunk & 3) * 64;
    const int tid   = threadIdx.x;
    const bool aside = (y < NB);
    const int rt    = y - NB;

    if (aside) {
        for (int s = 0; s < NS; s++) {
            int idx = __ldg(&inptensor[y*NS + s]);
            a_tile[s*257 + tid] = __ldg(&EmbA[(size_t)idx*ND + tid]);
        }
    } else {
        for (int s = 0; s < NS; s++) {
            int row = rt*128 + s;
            int rr = (row < VO) ? row : 0;
            a_tile[s*257 + tid] = __ldg(&EmbB[(size_t)rr*ND + tid]);
        }
    }
    __syncthreads();

    const int tr = tid >> 3;
    const int tc = tid & 7;

    float acc[4][8];
    #pragma unroll
    for (int i = 0; i < 4; i++)
        #pragma unroll
        for (int j = 0; j < 8; j++) acc[i][j] = 0.f;

    for (int k0 = 0; k0 < ND; k0 += 16) {
        #pragma unroll
        for (int t = 0; t < 4; t++) {
            int idx2 = tid + 256*t;
            int kk = idx2 >> 6, gg = idx2 & 63;
            int row = k0 + kk + (m == 2 ? 256 : 0);
            const float* Wsrc = (m == 0) ? FW : GW;
            wst[idx2] = __ldg(&Wsrc[row*256 + gbase + gg]);
        }
        __syncthreads();
        #pragma unroll
        for (int kk = 0; kk < 16; kk++) {
            float av[4], wv[8];
            #pragma unroll
            for (int i = 0; i < 4; i++) av[i] = a_tile[(tr + 32*i)*257 + k0 + kk];
            #pragma unroll
            for (int j = 0; j < 8; j++) wv[j] = wst[kk*64 + tc + 8*j];
            #pragma unroll
            for (int i = 0; i < 4; i++)
                #pragma unroll
                for (int j = 0; j < 8; j++) acc[i][j] += av[i]*wv[j];
        }
        __syncthreads();
    }

    float* outp;
    size_t obase;
    if (aside) {
        outp = (m == 0) ? g_am : (m == 1 ? g_aG1 : g_aG2);
        obase = (size_t)y*NS*ND;
    } else {
        outp = (m == 0) ? g_bm : (m == 1 ? g_bg1 : g_bg2);
        obase = (size_t)rt*128*ND;
    }
    #pragma unroll
    for (int j = 0; j < 8; j++) {
        int g = gbase + tc + 8*j;
        float bias = (m == 0) ? __ldg(&Fb[g]) : (m == 1 ? __ldg(&Gb[g]) : 0.f);
        #pragma unroll
        for (int i = 0; i < 4; i++) {
            float v = acc[i][j] + bias;
            if (m == 0) v = fmaxf(v, 0.f);
            if (m != 1) v = rtf(v);          // MMA-operand tables: round once
            outp[obase + (size_t)(tr + 32*i)*ND + g] = v;
        }
    }
}

// =========================================================================
// Pair kernel: one CTA per (b,c). 256 threads.
// Phases: gather tables -> P3 logits -> softmaxes -> P6 y1 -> P7 y2.
// =========================================================================
__global__ void __launch_bounds__(256) pair_kernel(
    const int*   __restrict__ cand,
    const float* __restrict__ HW,
    const float* __restrict__ Hb,
    float*       __restrict__ out)
{
    extern __shared__ float sm[];
    float* s_bbG2 = sm + OFF_BG2;    // [64][264]  (tf32 values)
    float* s_bm   = sm + OFF_BM;     // [64][260]  (tf32 values)
    float* s_beta = sm + OFF_BETA;   // [128][68]
    float* s_e    = sm + OFF_E;      // [128][72]
    int*   s_cid  = (int*)(sm + OFF_CID);
    float* sHW    = sm + OFF_HW;
    float* sRed   = sm + OFF_RED;

    const int tid  = threadIdx.x;
    const int p    = blockIdx.x;
    const int b    = p >> 6;
    const int w    = tid >> 5;
    const int lane = tid & 31;
    const int r    = lane >> 2;
    const int c    = lane & 3;

    sHW[tid] = __ldg(&HW[tid]);
    sHW[tid + 256] = __ldg(&HW[tid + 256]);

    // ---- P1: gather b_m and bbG2 rows from precomputed tables ----
    {
        const int* ci = cand + p*NZ;
        if (tid < 64) s_cid[tid] = __ldg(&ci[tid]);
        for (int z = 0; z < NZ; z++) {
            int idx = __ldg(&ci[z]);
            s_bm  [z*PBM + tid] = __ldg(&g_bm [(size_t)idx*ND + tid]);
            s_bbG2[z*PW  + tid] = __ldg(&g_bg2[(size_t)idx*ND + tid]);
        }
    }
    __syncthreads();

    // ---- P3: e[s][z] = a_m @ b_m^T (tf32 mma, K=256) -> s_e (fp32) ----
    {
        const int wm = w >> 1;      // 0..3
        const int wn = w & 1;       // 0..1
        float acc[2][4][4];
        #pragma unroll
        for (int mi=0;mi<2;mi++)
            #pragma unroll
            for (int f=0;f<4;f++)
                #pragma unroll
                for (int e=0;e<4;e++) acc[mi][f][e]=0.f;

        const float* amg = g_am + (size_t)b*NS*ND;
        stage_am(amg, sm + OFF_STG3, 0, tid);
        __syncthreads();
        for (int t = 0; t < 16; t++){
            const float* ca = sm + OFF_STG3 + (t&1)*STG_AM;
            if (t < 15) stage_am(amg, sm + OFF_STG3 + ((t+1)&1)*STG_AM, (t+1)*16, tid);
            #pragma unroll
            for (int kh = 0; kh < 2; kh++){
                int kg = t*16 + kh*8;
                int kl = kh*8;
                uint32_t afr[2][4];
                #pragma unroll
                for (int mi = 0; mi < 2; mi++){
                    const float* ap = ca + (wm*32 + mi*16 + r)*PAM + kl + c;
                    afr[mi][0]=ldu(ap);        afr[mi][1]=ldu(ap+8*PAM);
                    afr[mi][2]=ldu(ap+4);      afr[mi][3]=ldu(ap+8*PAM+4);
                }
                #pragma unroll
                for (int f = 0; f < 4; f++){
                    const float* bp = s_bm + (wn*32 + f*8 + r)*PBM + kg + c;
                    uint32_t b0 = ldu(bp);
                    uint32_t b1 = ldu(bp+4);
                    mma8(acc[0][f], afr[0][0],afr[0][1],afr[0][2],afr[0][3], b0,b1);
                    mma8(acc[1][f], afr[1][0],afr[1][1],afr[1][2],afr[1][3], b0,b1);
                }
            }
            __syncthreads();
        }
        #pragma unroll
        for (int mi=0;mi<2;mi++)
            #pragma unroll
            for (int f=0;f<4;f++){
                int row0 = wm*32 + mi*16 + r;
                int col0 = wn*32 + f*8 + c*2;
                s_e[row0*PE + col0]       = acc[mi][f][0];
                s_e[row0*PE + col0+1]     = acc[mi][f][1];
                s_e[(row0+8)*PE + col0]   = acc[mi][f][2];
                s_e[(row0+8)*PE + col0+1] = acc[mi][f][3];
            }
    }
    __syncthreads();

    // ---- P4a: beta = softmax over z (rows) -> s_beta (tf32 values) ----
    {
        for (int rr = 0; rr < 16; rr++) {
            int s = w*16 + rr;
            float v0 = s_e[s*PE + lane];
            float v1 = s_e[s*PE + lane + 32];
            float mx = fmaxf(v0, v1);
            #pragma unroll
            for (int off = 16; off >= 1; off >>= 1)
                mx = fmaxf(mx, __shfl_xor_sync(0xffffffffu, mx, off));
            float e0 = expf(v0 - mx), e1 = expf(v1 - mx);
            float ss = e0 + e1;
            #pragma unroll
            for (int off = 16; off >= 1; off >>= 1)
                ss += __shfl_xor_sync(0xffffffffu, ss, off);
            float inv = 1.f / ss;
            s_beta[s*PBETA + lane]      = rtf(e0 * inv);
            s_beta[s*PBETA + lane + 32] = rtf(e1 * inv);
        }
    }
    __syncthreads();

    // ---- P4b: alpha = softmax over s (cols), in place (tf32 values) ----
    {
        const int z = tid >> 2, q = tid & 3;
        float mx = -1e30f;
        float ev[32];
        #pragma unroll
        for (int i = 0; i < 32; i++) {
            ev[i] = s_e[(q*32 + i)*PE + z];
            mx = fmaxf(mx, ev[i]);
        }
        mx = fmaxf(mx, __shfl_xor_sync(0xffffffffu, mx, 1));
        mx = fmaxf(mx, __shfl_xor_sync(0xffffffffu, mx, 2));
        float ss = 0.f;
        #pragma unroll
        for (int i = 0; i < 32; i++) { ev[i] = expf(ev[i] - mx); ss += ev[i]; }
        ss += __shfl_xor_sync(0xffffffffu, ss, 1);
        ss += __shfl_xor_sync(0xffffffffu, ss, 2);
        float inv = 1.f / ss;
        #pragma unroll
        for (int i = 0; i < 32; i++)
            s_e[(q*32 + i)*PE + z] = rtf(ev[i] * inv);
    }
    __syncthreads();

    float y_local = 0.f;
    const float* HbP = Hb;

    // ---- P6: y1 += sum relu(aG1 + beta @ bbG2) * HW1  (K=64 over z) ----
    {
        const int wm = w >> 1;      // 0..3
        const int wn = w & 1;       // 0..1
        const float* aG1p = g_aG1 + (size_t)b*NS*ND;
        #pragma unroll
        for (int pass = 0; pass < 2; pass++){
            int nb = wn*128 + pass*64;
            float acc[2][8][4];
            #pragma unroll
            for (int mi=0;mi<2;mi++)
                #pragma unroll
                for (int f=0;f<8;f++)
                    #pragma unroll
                    for (int e=0;e<4;e++) acc[mi][f][e]=0.f;
            #pragma unroll
            for (int k8 = 0; k8 < 8; k8++){
                int k0 = k8*8;
                uint32_t afr[2][4];
                #pragma unroll
                for (int mi = 0; mi < 2; mi++){
                    const float* ap = s_beta + (wm*32 + mi*16 + r)*PBETA + k0 + c;
                    afr[mi][0]=ldu(ap);        afr[mi][1]=ldu(ap+8*PBETA);
                    afr[mi][2]=ldu(ap+4);      afr[mi][3]=ldu(ap+8*PBETA+4);
                }
                #pragma unroll
                for (int f = 0; f < 8; f++){
                    const float* bp = s_bbG2 + (k0 + c)*PW + nb + f*8 + r;
                    uint32_t b0 = ldu(bp);
                    uint32_t b1 = ldu(bp+4*PW);
                    mma8(acc[0][f], afr[0][0],afr[0][1],afr[0][2],afr[0][3], b0,b1);
                    mma8(acc[1][f], afr[1][0],afr[1][1],afr[1][2],afr[1][3], b0,b1);
                }
            }
            #pragma unroll
            for (int mi=0;mi<2;mi++)
                #pragma unroll
                for (int f=0;f<8;f++){
                    int row0 = wm*32 + mi*16 + r;
                    int col0 = nb + f*8 + c*2;
                    float2 g0 = __ldg((const float2*)(aG1p + (size_t)row0*ND + col0));
                    float2 g1 = __ldg((const float2*)(aG1p + (size_t)(row0+8)*ND + col0));
                    float h0 = sHW[col0], h1 = sHW[col0+1];
                    y_local += fmaxf(acc[mi][f][0] + g0.x, 0.f)*h0
                             + fmaxf(acc[mi][f][1] + g0.y, 0.f)*h1
                             + fmaxf(acc[mi][f][2] + g1.x, 0.f)*h0
                             + fmaxf(acc[mi][f][3] + g1.y, 0.f)*h1;
                }
        }
    }
    __syncthreads();

    // ---- P7: y2 += sum relu(bG1[gathered] + alpha^T @ aG2) * HW2 ----
    {
        const int wm = w >> 2;      // 0..1 -> z block of 32
        const int wn = w & 3;       // 0..3 -> g block of 64
        float acc[2][8][4];
        // init accumulators from gathered exact bG1 (= bb@GW1 + Gb)
        #pragma unroll
        for (int mi=0;mi<2;mi++)
            #pragma unroll
            for (int f=0;f<8;f++){
                int row0 = wm*32 + mi*16 + r;
                int col0 = wn*64 + f*8 + c*2;
                int id0 = s_cid[row0], id1 = s_cid[row0+8];
                float2 u0 = __ldg((const float2*)(g_bg1 + (size_t)id0*ND + col0));
                float2 u1 = __ldg((const float2*)(g_bg1 + (size_t)id1*ND + col0));
                acc[mi][f][0]=u0.x; acc[mi][f][1]=u0.y;
                acc[mi][f][2]=u1.x; acc[mi][f][3]=u1.y;
            }
        // alpha^T @ aG2 (K=128 over s)
        const float* aG2g = g_aG2 + (size_t)b*NS*ND;
        stage_w(aG2g, sm + OFF_STG7, 0, tid);
        __syncthreads();
        for (int t = 0; t < 8; t++){
            const float* cw = sm + OFF_STG7 + (t&1)*STG_BUF;
            if (t < 7) stage_w(aG2g, sm + OFF_STG7 + ((t+1)&1)*STG_BUF, (t+1)*16, tid);
            #pragma unroll
            for (int kh = 0; kh < 2; kh++){
                int kg = t*16 + kh*8;   // global s
                int kl = kh*8;
                uint32_t afr[2][4];
                #pragma unroll
                for (int mi = 0; mi < 2; mi++){
                    int m0 = wm*32 + mi*16;
                    const float* ap = s_e + (kg + c)*PE + m0 + r;
                    afr[mi][0]=ldu(ap);
                    afr[mi][1]=ldu(ap+8);
                    afr[mi][2]=ldu(ap+4*PE);
                    afr[mi][3]=ldu(ap+4*PE+8);
                }
                #pragma unroll
                for (int f = 0; f < 8; f++){
                    const float* bp = cw + (kl + c)*PW + wn*64 + f*8 + r;
                    uint32_t b0 = ldu(bp);
                    uint32_t b1 = ldu(bp+4*PW);
                    mma8(acc[0][f], afr[0][0],afr[0][1],afr[0][2],afr[0][3], b0,b1);
                    mma8(acc[1][f], afr[1][0],afr[1][1],afr[1][2],afr[1][3], b0,b1);
                }
            }
            __syncthreads();
        }
        #pragma unroll
        for (int mi=0;mi<2;mi++)
            #pragma unroll
            for (int f=0;f<8;f++){
                int col0 = wn*64 + f*8 + c*2;
                float h0 = sHW[256+col0], h1 = sHW[256+col0+1];
                y_local += fmaxf(acc[mi][f][0], 0.f)*h0
                         + fmaxf(acc[mi][f][1], 0.f)*h1
                         + fmaxf(acc[mi][f][2], 0.f)*h0
                         + fmaxf(acc[mi][f][3], 0.f)*h1;
            }
    }
    __syncthreads();

    // ---- block reduce ----
    {
        #pragma unroll
        for (int off = 16; off >= 1; off >>= 1)
            y_local += __shfl_xor_sync(0xffffffffu, y_local, off);
        if (lane == 0) sRed[w] = y_local;
        __syncthreads();
        if (tid == 0) {
            float t = 0.f;
            #pragma unroll
            for (int ww = 0; ww < 8; ww++) t += sRed[ww];
            out[p] = t + __ldg(&HbP[0]);
        }
    }
}

// =========================================================================
extern "C" void kernel_launch(void* const* d_in, const int* in_sizes, int n_in,
                              void* d_out, int out_size)
{
    const int*   inptensor = (const int*)  d_in[0];
    const int*   cand      = (const int*)  d_in[1];
    const float* EmbA      = (const float*)d_in[4];
    const float* EmbB      = (const float*)d_in[5];
    const float* FW        = (const float*)d_in[6];
    const float* Fb        = (const float*)d_in[7];
    const float* GW        = (const float*)d_in[8];
    const float* Gb        = (const float*)d_in[9];
    const float* HW        = (const float*)d_in[10];
    const float* Hb        = (const float*)d_in[11];
    float*       out       = (float*)d_out;

    (void)in_sizes; (void)n_in; (void)out_size;

    const int smem1 = (128*257 + 16*64) * 4;   // 135680 B
    const int smem2 = SMEM_FL * 4;             // 208160 B
    cudaFuncSetAttribute(tables_kernel, cudaFuncAttributeMaxDynamicSharedMemorySize, smem1);
    cudaFuncSetAttribute(pair_kernel,   cudaFuncAttributeMaxDynamicSharedMemorySize, smem2);

    tables_kernel<<<dim3(12, NB + (VOP/128)), 256, smem1>>>(
        inptensor, EmbA, EmbB, FW, Fb, GW, Gb);
    pair_kernel<<<NB*NC, 256, smem2>>>(cand, HW, Hb, out);
}

// round 5
// speedup vs baseline: 3.9909x; 1.1477x over previous
#include <cuda_runtime.h>
#include <cstdint>

#define NB 32
#define NC 64
#define NS 128
#define NZ 64
#define ND 256
#define VO 5000
#define VOP 5120

// pitches (floats) — conflict-free for their fragment patterns
#define PBM   260
#define PW    264
#define PE    72
#define PBETA 68
#define PAM   20

// pair-kernel smem float offsets
#define OFF_BG2  0            // bbG2 [64][264] = 16896
#define OFF_BM   16896        // b_m  [64][260] = 16640 ; P7 staging reuses
#define OFF_STG7 16896
#define OFF_BETA 33536        // beta [128][68] = 8704 ; P3 staging lives here first
#define OFF_STG3 33536
#define OFF_E    42240        // e/alpha [128][72] = 9216
#define OFF_CID  51456        // 64 ints
#define OFF_HW   51520        // 512
#define OFF_RED  52032        // 16
#define SMEM_FL  52048
#define STG_BUF  4224         // 16*264
#define STG_AM   2560         // 128*20

// ---------------- device scratch ----------------
__device__ float g_am [NB*NS*ND];
__device__ float g_aG1[NB*NS*ND];
__device__ float g_aG2[NB*NS*ND];
__device__ float g_bm [VOP*ND];
__device__ float g_bg1[VOP*ND];
__device__ float g_bg2[VOP*ND];

// ---------------- helpers ----------------
__device__ __forceinline__ uint32_t f2t(float f){
    uint32_t u; asm("cvt.rna.tf32.f32 %0, %1;" : "=r"(u) : "f"(f)); return u;
}
__device__ __forceinline__ float rtf(float f){ return __uint_as_float(f2t(f)); }
__device__ __forceinline__ uint32_t ldu(const float* p){ return __float_as_uint(*p); }

// A-frag order (m16n8k8.tf32): a0=(r,c) a1=(r+8,c) a2=(r,c+4) a3=(r+8,c+4)
__device__ __forceinline__ void mma8(float* d,
    uint32_t a0,uint32_t a1,uint32_t a2,uint32_t a3, uint32_t b0,uint32_t b1){
    asm volatile("mma.sync.aligned.m16n8k8.row.col.f32.tf32.tf32.f32 "
        "{%0,%1,%2,%3}, {%4,%5,%6,%7}, {%8,%9}, {%0,%1,%2,%3};\n"
        : "+f"(d[0]),"+f"(d[1]),"+f"(d[2]),"+f"(d[3])
        : "r"(a0),"r"(a1),"r"(a2),"r"(a3),"r"(b0),"r"(b1));
}

// stage [16][256] gmem tile into smem [16][264] — 512 threads
__device__ __forceinline__ void stage_w(const float* __restrict__ g, float* s,
                                        int k0, int tid){
    int kk = tid >> 5;
    int c4 = (tid & 31) * 8;
    const float4* gp = (const float4*)(g + (size_t)(k0+kk)*256 + c4);
    float4 v0 = __ldg(gp), v1 = __ldg(gp+1);
    float* sp = s + kk*PW + c4;
    *(float4*)(sp) = v0; *(float4*)(sp+4) = v1;
}

// stage a_m k-tile [128][16] into smem [128][20] — 512 threads
__device__ __forceinline__ void stage_am(const float* __restrict__ g, float* s,
                                         int k0, int tid){
    int srow = tid >> 2;
    int kc = (tid & 3) * 4;
    float4 v = __ldg((const float4*)(g + (size_t)srow*ND + k0 + kc));
    *(float4*)(s + srow*PAM + kc) = v;
}

// =========================================================================
// Tables kernel (exact fp32 FFMA). 64-row tiles -> 69 KB smem, 2 CTAs/SM.
// grid = (12, 144): y<64 -> a-side (b=y>>1, half=y&1); else vocab tile rt=y-64.
// chunk: m = chunk>>2 (0: F+relu, 1: GW1+Gb, 2: GW2), g-chunk of 64.
// =========================================================================
__global__ void __launch_bounds__(256) tables_kernel(
    const int*   __restrict__ inptensor,
    const float* __restrict__ EmbA,
    const float* __restrict__ EmbB,
    const float* __restrict__ FW,
    const float* __restrict__ Fb,
    const float* __restrict__ GW,
    const float* __restrict__ Gb)
{
    extern __shared__ float sm[];
    float* a_tile = sm;              // 64*257
    float* wst    = sm + 64*257;     // 16*64

    const int y     = blockIdx.y;
    const int chunk = blockIdx.x;
    const int m     = chunk >> 2;
    const int gbase = (chunk & 3) * 64;
    const int tid   = threadIdx.x;
    const bool aside = (y < 2*NB);

    if (aside) {
        const int b = y >> 1, sh = (y & 1) * 64;
        for (int s = 0; s < 64; s++) {
            int idx = __ldg(&inptensor[b*NS + sh + s]);
            a_tile[s*257 + tid] = __ldg(&EmbA[(size_t)idx*ND + tid]);
        }
    } else {
        const int rt = y - 2*NB;
        for (int s = 0; s < 64; s++) {
            int row = rt*64 + s;
            int rr = (row < VO) ? row : 0;
            a_tile[s*257 + tid] = __ldg(&EmbB[(size_t)rr*ND + tid]);
        }
    }
    __syncthreads();

    const int tr = tid >> 3;   // 0..31
    const int tc = tid & 7;

    float acc[2][8];
    #pragma unroll
    for (int i = 0; i < 2; i++)
        #pragma unroll
        for (int j = 0; j < 8; j++) acc[i][j] = 0.f;

    for (int k0 = 0; k0 < ND; k0 += 16) {
        #pragma unroll
        for (int t = 0; t < 4; t++) {
            int idx2 = tid + 256*t;
            int kk = idx2 >> 6, gg = idx2 & 63;
            int row = k0 + kk + (m == 2 ? 256 : 0);
            const float* Wsrc = (m == 0) ? FW : GW;
            wst[idx2] = __ldg(&Wsrc[row*256 + gbase + gg]);
        }
        __syncthreads();
        #pragma unroll
        for (int kk = 0; kk < 16; kk++) {
            float av[2], wv[8];
            #pragma unroll
            for (int i = 0; i < 2; i++) av[i] = a_tile[(tr + 32*i)*257 + k0 + kk];
            #pragma unroll
            for (int j = 0; j < 8; j++) wv[j] = wst[kk*64 + tc + 8*j];
            #pragma unroll
            for (int i = 0; i < 2; i++)
                #pragma unroll
                for (int j = 0; j < 8; j++) acc[i][j] += av[i]*wv[j];
        }
        __syncthreads();
    }

    float* outp;
    size_t obase;
    if (aside) {
        const int b = y >> 1, sh = (y & 1) * 64;
        outp = (m == 0) ? g_am : (m == 1 ? g_aG1 : g_aG2);
        obase = (size_t)b*NS*ND + (size_t)sh*ND;
    } else {
        const int rt = y - 2*NB;
        outp = (m == 0) ? g_bm : (m == 1 ? g_bg1 : g_bg2);
        obase = (size_t)rt*64*ND;
    }
    #pragma unroll
    for (int j = 0; j < 8; j++) {
        int g = gbase + tc + 8*j;
        float bias = (m == 0) ? __ldg(&Fb[g]) : (m == 1 ? __ldg(&Gb[g]) : 0.f);
        #pragma unroll
        for (int i = 0; i < 2; i++) {
            float v = acc[i][j] + bias;
            if (m == 0) v = fmaxf(v, 0.f);
            if (m != 1) v = rtf(v);
            outp[obase + (size_t)(tr + 32*i)*ND + g] = v;
        }
    }
}

// =========================================================================
// Pair kernel: one CTA per (b,c). 512 threads / 16 warps.
// =========================================================================
__global__ void __launch_bounds__(512) pair_kernel(
    const int*   __restrict__ cand,
    const float* __restrict__ HW,
    const float* __restrict__ Hb,
    float*       __restrict__ out)
{
    extern __shared__ float sm[];
    float* s_bbG2 = sm + OFF_BG2;    // [64][264]
    float* s_bm   = sm + OFF_BM;     // [64][260]
    float* s_beta = sm + OFF_BETA;   // [128][68]
    float* s_e    = sm + OFF_E;      // [128][72]
    int*   s_cid  = (int*)(sm + OFF_CID);
    float* sHW    = sm + OFF_HW;
    float* sRed   = sm + OFF_RED;

    const int tid  = threadIdx.x;
    const int p    = blockIdx.x;
    const int b    = p >> 6;
    const int w    = tid >> 5;
    const int lane = tid & 31;
    const int r    = lane >> 2;
    const int c    = lane & 3;

    if (tid < 512) { if (tid < 256) { sHW[tid] = __ldg(&HW[tid]); sHW[tid+256] = __ldg(&HW[tid+256]); } }

    // ---- P1: gather b_m and bbG2 rows (two thread-halves in parallel) ----
    {
        const int* ci = cand + p*NZ;
        if (tid < 64) s_cid[tid] = __ldg(&ci[tid]);
        const int half = tid >> 8;
        const int col  = tid & 255;
        for (int z = 0; z < NZ; z++) {
            int idx = __ldg(&ci[z]);
            if (half == 0) s_bm  [z*PBM + col] = __ldg(&g_bm [(size_t)idx*ND + col]);
            else           s_bbG2[z*PW  + col] = __ldg(&g_bg2[(size_t)idx*ND + col]);
        }
    }
    __syncthreads();

    // ---- P3: e[s][z] = a_m @ b_m^T (K=256) -> s_e ----
    {
        const int wm = w >> 1;      // 0..7  (m16 tile)
        const int wn = w & 1;       // 0..1  (4 n8 tiles)
        float acc[4][4];
        #pragma unroll
        for (int f=0;f<4;f++)
            #pragma unroll
            for (int e=0;e<4;e++) acc[f][e]=0.f;

        const float* amg = g_am + (size_t)b*NS*ND;
        stage_am(amg, sm + OFF_STG3, 0, tid);
        __syncthreads();
        for (int t = 0; t < 16; t++){
            const float* ca = sm + OFF_STG3 + (t&1)*STG_AM;
            if (t < 15) stage_am(amg, sm + OFF_STG3 + ((t+1)&1)*STG_AM, (t+1)*16, tid);
            #pragma unroll
            for (int kh = 0; kh < 2; kh++){
                int kg = t*16 + kh*8;
                int kl = kh*8;
                const float* ap = ca + (wm*16 + r)*PAM + kl + c;
                uint32_t a0=ldu(ap), a1=ldu(ap+8*PAM), a2=ldu(ap+4), a3=ldu(ap+8*PAM+4);
                #pragma unroll
                for (int f = 0; f < 4; f++){
                    const float* bp = s_bm + (wn*32 + f*8 + r)*PBM + kg + c;
                    mma8(acc[f], a0,a1,a2,a3, ldu(bp), ldu(bp+4));
                }
            }
            __syncthreads();
        }
        #pragma unroll
        for (int f=0;f<4;f++){
            int row0 = wm*16 + r;
            int col0 = wn*32 + f*8 + c*2;
            s_e[row0*PE + col0]       = acc[f][0];
            s_e[row0*PE + col0+1]     = acc[f][1];
            s_e[(row0+8)*PE + col0]   = acc[f][2];
            s_e[(row0+8)*PE + col0+1] = acc[f][3];
        }
    }
    __syncthreads();

    // ---- P4a: beta = softmax over z (rows) -> s_beta (tf32) ----
    {
        for (int rr = 0; rr < 8; rr++) {
            int s = w*8 + rr;
            float v0 = s_e[s*PE + lane];
            float v1 = s_e[s*PE + lane + 32];
            float mx = fmaxf(v0, v1);
            #pragma unroll
            for (int off = 16; off >= 1; off >>= 1)
                mx = fmaxf(mx, __shfl_xor_sync(0xffffffffu, mx, off));
            float e0 = expf(v0 - mx), e1 = expf(v1 - mx);
            float ss = e0 + e1;
            #pragma unroll
            for (int off = 16; off >= 1; off >>= 1)
                ss += __shfl_xor_sync(0xffffffffu, ss, off);
            float inv = 1.f / ss;
            s_beta[s*PBETA + lane]      = rtf(e0 * inv);
            s_beta[s*PBETA + lane + 32] = rtf(e1 * inv);
        }
    }
    __syncthreads();

    // ---- P4b: alpha = softmax over s (cols), in place (tf32) ----
    {
        const int z = tid >> 3, q = tid & 7;     // 8 threads per column
        float mx = -1e30f;
        float ev[16];
        #pragma unroll
        for (int i = 0; i < 16; i++) {
            ev[i] = s_e[(q*16 + i)*PE + z];
            mx = fmaxf(mx, ev[i]);
        }
        mx = fmaxf(mx, __shfl_xor_sync(0xffffffffu, mx, 1));
        mx = fmaxf(mx, __shfl_xor_sync(0xffffffffu, mx, 2));
        mx = fmaxf(mx, __shfl_xor_sync(0xffffffffu, mx, 4));
        float ss = 0.f;
        #pragma unroll
        for (int i = 0; i < 16; i++) { ev[i] = expf(ev[i] - mx); ss += ev[i]; }
        ss += __shfl_xor_sync(0xffffffffu, ss, 1);
        ss += __shfl_xor_sync(0xffffffffu, ss, 2);
        ss += __shfl_xor_sync(0xffffffffu, ss, 4);
        float inv = 1.f / ss;
        #pragma unroll
        for (int i = 0; i < 16; i++)
            s_e[(q*16 + i)*PE + z] = rtf(ev[i] * inv);
    }
    __syncthreads();

    float y_local = 0.f;

    // ---- P6: y1 += sum relu(aG1 + beta @ bbG2) * HW1  (K=64 over z) ----
    {
        const int wm = w >> 2;      // 0..3 -> s block of 32
        const int wn = w & 3;       // 0..3 -> g block of 64
        const float* aG1p = g_aG1 + (size_t)b*NS*ND;
        float acc[2][8][4];
        #pragma unroll
        for (int mi=0;mi<2;mi++)
            #pragma unroll
            for (int f=0;f<8;f++)
                #pragma unroll
                for (int e=0;e<4;e++) acc[mi][f][e]=0.f;
        #pragma unroll
        for (int k8 = 0; k8 < 8; k8++){
            int k0 = k8*8;
            uint32_t afr[2][4];
            #pragma unroll
            for (int mi = 0; mi < 2; mi++){
                const float* ap = s_beta + (wm*32 + mi*16 + r)*PBETA + k0 + c;
                afr[mi][0]=ldu(ap);   afr[mi][1]=ldu(ap+8*PBETA);
                afr[mi][2]=ldu(ap+4); afr[mi][3]=ldu(ap+8*PBETA+4);
            }
            #pragma unroll
            for (int f = 0; f < 8; f++){
                const float* bp = s_bbG2 + (k0 + c)*PW + wn*64 + f*8 + r;
                uint32_t b0 = ldu(bp), b1 = ldu(bp+4*PW);
                mma8(acc[0][f], afr[0][0],afr[0][1],afr[0][2],afr[0][3], b0,b1);
                mma8(acc[1][f], afr[1][0],afr[1][1],afr[1][2],afr[1][3], b0,b1);
            }
        }
        #pragma unroll
        for (int mi=0;mi<2;mi++)
            #pragma unroll
            for (int f=0;f<8;f++){
                int row0 = wm*32 + mi*16 + r;
                int col0 = wn*64 + f*8 + c*2;
                float2 g0 = __ldg((const float2*)(aG1p + (size_t)row0*ND + col0));
                float2 g1 = __ldg((const float2*)(aG1p + (size_t)(row0+8)*ND + col0));
                float h0 = sHW[col0], h1 = sHW[col0+1];
                y_local += fmaxf(acc[mi][f][0] + g0.x, 0.f)*h0
                         + fmaxf(acc[mi][f][1] + g0.y, 0.f)*h1
                         + fmaxf(acc[mi][f][2] + g1.x, 0.f)*h0
                         + fmaxf(acc[mi][f][3] + g1.y, 0.f)*h1;
            }
    }
    __syncthreads();

    // ---- P7: y2 += sum relu(bG1[gathered] + alpha^T @ aG2) * HW2 ----
    {
        const int wm = w >> 3;      // 0..1 -> z block of 32
        const int wn = w & 7;       // 0..7 -> g block of 32
        float acc[2][4][4];
        #pragma unroll
        for (int mi=0;mi<2;mi++)
            #pragma unroll
            for (int f=0;f<4;f++){
                int row0 = wm*32 + mi*16 + r;
                int col0 = wn*32 + f*8 + c*2;
                int id0 = s_cid[row0], id1 = s_cid[row0+8];
                float2 u0 = __ldg((const float2*)(g_bg1 + (size_t)id0*ND + col0));
                float2 u1 = __ldg((const float2*)(g_bg1 + (size_t)id1*ND + col0));
                acc[mi][f][0]=u0.x; acc[mi][f][1]=u0.y;
                acc[mi][f][2]=u1.x; acc[mi][f][3]=u1.y;
            }
        const float* aG2g = g_aG2 + (size_t)b*NS*ND;
        stage_w(aG2g, sm + OFF_STG7, 0, tid);
        __syncthreads();
        for (int t = 0; t < 8; t++){
            const float* cw = sm + OFF_STG7 + (t&1)*STG_BUF;
            if (t < 7) stage_w(aG2g, sm + OFF_STG7 + ((t+1)&1)*STG_BUF, (t+1)*16, tid);
            #pragma unroll
            for (int kh = 0; kh < 2; kh++){
                int kg = t*16 + kh*8;   // global s
                int kl = kh*8;
                uint32_t afr[2][4];
                #pragma unroll
                for (int mi = 0; mi < 2; mi++){
                    int m0 = wm*32 + mi*16;
                    const float* ap = s_e + (kg + c)*PE + m0 + r;
                    afr[mi][0]=ldu(ap);
                    afr[mi][1]=ldu(ap+8);
                    afr[mi][2]=ldu(ap+4*PE);
                    afr[mi][3]=ldu(ap+4*PE+8);
                }
                #pragma unroll
                for (int f = 0; f < 4; f++){
                    const float* bp = cw + (kl + c)*PW + wn*32 + f*8 + r;
                    uint32_t b0 = ldu(bp), b1 = ldu(bp+4*PW);
                    mma8(acc[0][f], afr[0][0],afr[0][1],afr[0][2],afr[0][3], b0,b1);
                    mma8(acc[1][f], afr[1][0],afr[1][1],afr[1][2],afr[1][3], b0,b1);
                }
            }
            __syncthreads();
        }
        #pragma unroll
        for (int mi=0;mi<2;mi++)
            #pragma unroll
            for (int f=0;f<4;f++){
                int col0 = wn*32 + f*8 + c*2;
                float h0 = sHW[256+col0], h1 = sHW[256+col0+1];
                y_local += fmaxf(acc[mi][f][0], 0.f)*h0
                         + fmaxf(acc[mi][f][1], 0.f)*h1
                         + fmaxf(acc[mi][f][2], 0.f)*h0
                         + fmaxf(acc[mi][f][3], 0.f)*h1;
            }
    }
    __syncthreads();

    // ---- block reduce (16 warps) ----
    {
        #pragma unroll
        for (int off = 16; off >= 1; off >>= 1)
            y_local += __shfl_xor_sync(0xffffffffu, y_local, off);
        if (lane == 0) sRed[w] = y_local;
        __syncthreads();
        if (tid == 0) {
            float t = 0.f;
            #pragma unroll
            for (int ww = 0; ww < 16; ww++) t += sRed[ww];
            out[p] = t + __ldg(&Hb[0]);
        }
    }
}

// =========================================================================
extern "C" void kernel_launch(void* const* d_in, const int* in_sizes, int n_in,
                              void* d_out, int out_size)
{
    const int*   inptensor = (const int*)  d_in[0];
    const int*   cand      = (const int*)  d_in[1];
    const float* EmbA      = (const float*)d_in[4];
    const float* EmbB      = (const float*)d_in[5];
    const float* FW        = (const float*)d_in[6];
    const float* Fb        = (const float*)d_in[7];
    const float* GW        = (const float*)d_in[8];
    const float* Gb        = (const float*)d_in[9];
    const float* HW        = (const float*)d_in[10];
    const float* Hb        = (const float*)d_in[11];
    float*       out       = (float*)d_out;

    (void)in_sizes; (void)n_in; (void)out_size;

    const int smem1 = (64*257 + 16*64) * 4;    // 69888 B -> 2 CTAs/SM
    const int smem2 = SMEM_FL * 4;             // 208192 B
    cudaFuncSetAttribute(tables_kernel, cudaFuncAttributeMaxDynamicSharedMemorySize, smem1);
    cudaFuncSetAttribute(pair_kernel,   cudaFuncAttributeMaxDynamicSharedMemorySize, smem2);

    tables_kernel<<<dim3(12, 2*NB + VOP/64), 256, smem1>>>(
        inptensor, EmbA, EmbB, FW, Fb, GW, Gb);
    pair_kernel<<<NB*NC, 512, smem2>>>(cand, HW, Hb, out);
}

// round 6
// speedup vs baseline: 5.0417x; 1.2633x over previous
#include <cuda_runtime.h>
#include <cuda_bf16.h>
#include <cstdint>

#define NB 32
#define NC 64
#define NS 128
#define NZ 64
#define ND 256
#define VO 5000
#define VOP 5120

typedef __nv_bfloat16 bf16;

// ---- pair-kernel smem byte offsets ----
// Region A (reused):  [am 128x264 bf16 | bm 64x264 bf16]  then  [bg2t 256x72 | stg7 256x136]
#define OB_AM    0         // 67584 B
#define OB_BM    67584     // 33792 B  (A region ends 101376)
#define OB_BG2T  0         // 36864 B
#define OB_STG7  36864     // 69632 B  (ends 106496)
#define OB_E     106496    // e fp32 [128][68] = 34816
#define OB_BETA  141312    // beta bf16 [128][72] = 18432
#define OB_ALPT  159744    // alphaT bf16 [64][136] = 17408
#define OB_CID   177152    // 64 ints
#define OB_HW    177408    // 512 fp32
#define OB_RED   179456    // 16 fp32
#define SMEM_PAIR 179520

// pitches (elements)
#define P_AM   264   // bf16, 132 words/row -> 4r+c banks
#define P_BM   264
#define P_E    68    // fp32
#define P_BETA 72    // bf16, 36 words -> 4r+c
#define P_BG2T 72
#define P_ALPT 136   // bf16, 68 words -> 4r+c
#define P_STG7 136

// ---------------- device scratch ----------------
__device__ bf16  g_am  [NB*NS*ND];   // bf16 relu(a@FW+Fb)       [b][s][k]
__device__ float g_aG1 [NB*NS*ND];   // exact a@GW1+Gb           [b][s][g]
__device__ bf16  g_aG2T[NB*ND*NS];   // bf16 (a@GW2)^T           [b][g][s]
__device__ bf16  g_bm  [VOP*ND];     // bf16 relu(EmbB@FW+Fb)    [v][k]
__device__ float g_bg1 [VOP*ND];     // exact EmbB@GW1+Gb        [v][g]
__device__ bf16  g_bg2 [VOP*ND];     // bf16 EmbB@GW2            [v][g]

// ---------------- helpers ----------------
__device__ __forceinline__ uint32_t ldb(const bf16* p){
    return *reinterpret_cast<const uint32_t*>(p);
}
__device__ __forceinline__ uint32_t pkf(float a, float b){
    __nv_bfloat162 t = __floats2bfloat162_rn(a, b);
    return *reinterpret_cast<uint32_t*>(&t);
}
__device__ __forceinline__ uint32_t pkh(bf16 a, bf16 b){
    __nv_bfloat162 t = __halves2bfloat162(a, b);
    return *reinterpret_cast<uint32_t*>(&t);
}
// mma m16n8k16 bf16: a0=(r,2c) a1=(r+8,2c) a2=(r,2c+8) a3=(r+8,2c+8); b0=B[n=r][k=2c] b1=[r][2c+8]
__device__ __forceinline__ void mmab(float* d,
    uint32_t a0,uint32_t a1,uint32_t a2,uint32_t a3, uint32_t b0,uint32_t b1){
    asm volatile("mma.sync.aligned.m16n8k16.row.col.f32.bf16.bf16.f32 "
        "{%0,%1,%2,%3}, {%4,%5,%6,%7}, {%8,%9}, {%0,%1,%2,%3};\n"
        : "+f"(d[0]),"+f"(d[1]),"+f"(d[2]),"+f"(d[3])
        : "r"(a0),"r"(a1),"r"(a2),"r"(a3),"r"(b0),"r"(b1));
}

// =========================================================================
// Tables kernel (exact fp32 FFMA, bf16/fp32 outputs). 64-row tiles, 2 CTA/SM.
// grid=(12, 144): y<64 -> a-side (b=y>>1, half=y&1); else vocab tile rt=y-64.
// m = chunk>>2: 0 F+relu (bf16), 1 GW1+Gb (fp32), 2 GW2 (bf16; a-side transposed)
// =========================================================================
__global__ void __launch_bounds__(256) tables_kernel(
    const int*   __restrict__ inptensor,
    const float* __restrict__ EmbA,
    const float* __restrict__ EmbB,
    const float* __restrict__ FW,
    const float* __restrict__ Fb,
    const float* __restrict__ GW,
    const float* __restrict__ Gb)
{
    extern __shared__ float sm[];
    float* a_tile = sm;              // 64*257
    float* wst    = sm + 64*257;     // 16*64

    const int y     = blockIdx.y;
    const int chunk = blockIdx.x;
    const int m     = chunk >> 2;
    const int gbase = (chunk & 3) * 64;
    const int tid   = threadIdx.x;
    const bool aside = (y < 2*NB);

    if (aside) {
        const int b = y >> 1, sh = (y & 1) * 64;
        for (int s = 0; s < 64; s++) {
            int idx = __ldg(&inptensor[b*NS + sh + s]);
            a_tile[s*257 + tid] = __ldg(&EmbA[(size_t)idx*ND + tid]);
        }
    } else {
        const int rt = y - 2*NB;
        for (int s = 0; s < 64; s++) {
            int row = rt*64 + s;
            int rr = (row < VO) ? row : 0;
            a_tile[s*257 + tid] = __ldg(&EmbB[(size_t)rr*ND + tid]);
        }
    }
    __syncthreads();

    const int tr = tid >> 3;   // 0..31 (row group)
    const int tc = tid & 7;    // 0..7  (8 consecutive g per thread)

    float acc[2][8];
    #pragma unroll
    for (int i = 0; i < 2; i++)
        #pragma unroll
        for (int j = 0; j < 8; j++) acc[i][j] = 0.f;

    for (int k0 = 0; k0 < ND; k0 += 16) {
        #pragma unroll
        for (int t = 0; t < 4; t++) {
            int idx2 = tid + 256*t;
            int kk = idx2 >> 6, gg = idx2 & 63;
            int row = k0 + kk + (m == 2 ? 256 : 0);
            const float* Wsrc = (m == 0) ? FW : GW;
            wst[idx2] = __ldg(&Wsrc[row*256 + gbase + gg]);
        }
        __syncthreads();
        #pragma unroll
        for (int kk = 0; kk < 16; kk++) {
            float av0 = a_tile[tr*257 + k0 + kk];
            float av1 = a_tile[(tr + 32)*257 + k0 + kk];
            const float4* wp = (const float4*)(wst + kk*64 + tc*8);
            float4 w0 = wp[0], w1 = wp[1];
            float wv[8] = {w0.x,w0.y,w0.z,w0.w,w1.x,w1.y,w1.z,w1.w};
            #pragma unroll
            for (int j = 0; j < 8; j++) { acc[0][j] += av0*wv[j]; acc[1][j] += av1*wv[j]; }
        }
        __syncthreads();
    }

    // biases
    float bias[8];
    #pragma unroll
    for (int j = 0; j < 8; j++) {
        int g = gbase + tc*8 + j;
        bias[j] = (m == 0) ? __ldg(&Fb[g]) : (m == 1 ? __ldg(&Gb[g]) : 0.f);
    }

    const int b_  = y >> 1, sh = (y & 1) * 64;
    const int rt  = y - 2*NB;

    #pragma unroll
    for (int i = 0; i < 2; i++) {
        int row = aside ? (sh + tr + 32*i) : (rt*64 + tr + 32*i);
        float v[8];
        #pragma unroll
        for (int j = 0; j < 8; j++) {
            v[j] = acc[i][j] + bias[j];
            if (m == 0) v[j] = fmaxf(v[j], 0.f);
        }
        if (m == 1) {
            float* out = aside ? (g_aG1 + (size_t)b_*NS*ND) : g_bg1;
            float4* o4 = (float4*)(out + (size_t)row*ND + gbase + tc*8);
            o4[0] = make_float4(v[0],v[1],v[2],v[3]);
            o4[1] = make_float4(v[4],v[5],v[6],v[7]);
        } else if (m == 2 && aside) {
            // transposed: g_aG2T[b][g][s]
            #pragma unroll
            for (int j = 0; j < 8; j++) {
                int g = gbase + tc*8 + j;
                g_aG2T[((size_t)b_*ND + g)*NS + row] = __float2bfloat16_rn(v[j]);
            }
        } else {
            bf16* out = (m == 0)
                ? (aside ? (g_am + (size_t)b_*NS*ND) : g_bm)
                : g_bg2;   // m==2 b-side
            uint32_t u[4];
            #pragma unroll
            for (int j = 0; j < 4; j++) u[j] = pkf(v[2*j], v[2*j+1]);
            uint4* o4 = (uint4*)(out + (size_t)row*ND + gbase + tc*8);
            *o4 = make_uint4(u[0],u[1],u[2],u[3]);
        }
    }
}

// =========================================================================
// Pair kernel: one CTA per (b,c). 512 threads / 16 warps. bf16 mma k16.
// Syncs: P1 | P3 | (softmax+gathers) | P6+P7 | reduce  -> 5 barriers total.
// =========================================================================
__global__ void __launch_bounds__(512) pair_kernel(
    const int*   __restrict__ cand,
    const float* __restrict__ HW,
    const float* __restrict__ Hb,
    float*       __restrict__ out)
{
    extern __shared__ char smc[];
    bf16*  s_am   = (bf16*) (smc + OB_AM);     // [128][264]
    bf16*  s_bm   = (bf16*) (smc + OB_BM);     // [64][264]
    bf16*  s_bg2t = (bf16*) (smc + OB_BG2T);   // [256][72]
    bf16*  s_stg7 = (bf16*) (smc + OB_STG7);   // [256][136]
    float* s_e    = (float*)(smc + OB_E);      // [128][68]
    bf16*  s_beta = (bf16*) (smc + OB_BETA);   // [128][72]
    bf16*  s_alpt = (bf16*) (smc + OB_ALPT);   // [64][136]
    int*   s_cid  = (int*)  (smc + OB_CID);
    float* sHW    = (float*)(smc + OB_HW);
    float* sRed   = (float*)(smc + OB_RED);

    const int tid  = threadIdx.x;
    const int p    = blockIdx.x;
    const int b    = p >> 6;
    const int w    = tid >> 5;
    const int lane = tid & 31;
    const int r    = lane >> 2;
    const int c    = lane & 3;

    if (tid < 256) { sHW[tid] = __ldg(&HW[tid]); sHW[tid+256] = __ldg(&HW[tid+256]); }
    if (tid < 64)  s_cid[tid] = __ldg(&cand[p*NZ + tid]);

    // ---- P1: stage a_m (full 128x256) + gather b_m rows ----
    {
        const uint4* src = (const uint4*)(g_am + (size_t)b*NS*ND);   // 4096 uint4
        #pragma unroll
        for (int t = 0; t < 8; t++) {
            int idx = tid + 512*t;
            int row = idx >> 5, c8 = (idx & 31) * 8;
            *(uint4*)(s_am + row*P_AM + c8) = __ldg(&src[idx]);
        }
        #pragma unroll
        for (int t = 0; t < 4; t++) {
            int idx = tid + 512*t;             // 2048
            int z = idx >> 5, c8 = (idx & 31) * 8;
            int id = __ldg(&cand[p*NZ + z]);
            *(uint4*)(s_bm + z*P_BM + c8) = __ldg((const uint4*)(g_bm + (size_t)id*ND + c8));
        }
    }
    __syncthreads();

    // ---- P3: e[s][z] = a_m @ b_m^T  (bf16 k16, K=256, no inner syncs) ----
    {
        const int wm = w >> 1;       // 0..7 -> s0 = wm*16
        const int wn = w & 1;        // 0..1 -> z block of 32 (4 n8 tiles)
        const int s0 = wm*16, zb = wn*32;
        float acc[4][4];
        #pragma unroll
        for (int f=0;f<4;f++){ acc[f][0]=0.f;acc[f][1]=0.f;acc[f][2]=0.f;acc[f][3]=0.f; }

        const bf16* ap0 = s_am + (s0 + r)*P_AM + 2*c;
        #pragma unroll 4
        for (int ks = 0; ks < 16; ks++) {
            const bf16* ap = ap0 + ks*16;
            uint32_t a0 = ldb(ap), a1 = ldb(ap + 8*P_AM), a2 = ldb(ap + 8), a3 = ldb(ap + 8*P_AM + 8);
            #pragma unroll
            for (int f = 0; f < 4; f++) {
                const bf16* bp = s_bm + (zb + f*8 + r)*P_BM + ks*16 + 2*c;
                mmab(acc[f], a0,a1,a2,a3, ldb(bp), ldb(bp+8));
            }
        }
        #pragma unroll
        for (int f = 0; f < 4; f++) {
            int col0 = zb + f*8 + 2*c;
            *(float2*)(s_e + (s0+r)*P_E + col0)   = make_float2(acc[f][0], acc[f][1]);
            *(float2*)(s_e + (s0+r+8)*P_E + col0) = make_float2(acc[f][2], acc[f][3]);
        }
    }
    __syncthreads();

    // ---- P4a: beta = softmax over z (rows) -> s_beta (bf16) ----
    {
        #pragma unroll
        for (int rr = 0; rr < 8; rr++) {
            int s = w*8 + rr;
            float v0 = s_e[s*P_E + lane];
            float v1 = s_e[s*P_E + lane + 32];
            float mx = fmaxf(v0, v1);
            #pragma unroll
            for (int off = 16; off >= 1; off >>= 1)
                mx = fmaxf(mx, __shfl_xor_sync(0xffffffffu, mx, off));
            float e0 = expf(v0 - mx), e1 = expf(v1 - mx);
            float ss = e0 + e1;
            #pragma unroll
            for (int off = 16; off >= 1; off >>= 1)
                ss += __shfl_xor_sync(0xffffffffu, ss, off);
            float inv = 1.f / ss;
            s_beta[s*P_BETA + lane]      = __float2bfloat16_rn(e0 * inv);
            s_beta[s*P_BETA + lane + 32] = __float2bfloat16_rn(e1 * inv);
        }
    }

    // ---- P4b: alpha = softmax over s (cols) -> s_alpt transposed (bf16) ----
    {
        const int z = tid >> 3, q = tid & 7;
        float ev[16];
        float mx = -1e30f;
        #pragma unroll
        for (int i = 0; i < 16; i++) {
            ev[i] = s_e[(q*16 + i)*P_E + z];
            mx = fmaxf(mx, ev[i]);
        }
        mx = fmaxf(mx, __shfl_xor_sync(0xffffffffu, mx, 1));
        mx = fmaxf(mx, __shfl_xor_sync(0xffffffffu, mx, 2));
        mx = fmaxf(mx, __shfl_xor_sync(0xffffffffu, mx, 4));
        float ss = 0.f;
        #pragma unroll
        for (int i = 0; i < 16; i++) { ev[i] = expf(ev[i] - mx); ss += ev[i]; }
        ss += __shfl_xor_sync(0xffffffffu, ss, 1);
        ss += __shfl_xor_sync(0xffffffffu, ss, 2);
        ss += __shfl_xor_sync(0xffffffffu, ss, 4);
        float inv = 1.f / ss;
        #pragma unroll
        for (int i = 0; i < 8; i++) {
            uint32_t u = pkf(ev[2*i]*inv, ev[2*i+1]*inv);
            *(uint32_t*)(s_alpt + z*P_ALPT + q*16 + 2*i) = u;
        }
    }

    // ---- gather bbG2^T [g][z] + stage aG2^T [g][s] (regions of dead am/bm) ----
    {
        const int half = tid >> 8;          // 0/1
        const int g    = tid & 255;
        #pragma unroll
        for (int t = 0; t < 16; t++) {
            int z0 = (half*16 + t) * 2;
            int id0 = s_cid[z0], id1 = s_cid[z0+1];
            bf16 v0 = __ldg(g_bg2 + (size_t)id0*ND + g);
            bf16 v1 = __ldg(g_bg2 + (size_t)id1*ND + g);
            *(uint32_t*)(s_bg2t + g*P_BG2T + z0) = pkh(v0, v1);
        }
        const uint4* src = (const uint4*)(g_aG2T + (size_t)b*ND*NS);   // 4096 uint4
        #pragma unroll
        for (int t = 0; t < 8; t++) {
            int idx = tid + 512*t;
            int gg = idx >> 4, c8 = (idx & 15) * 8;
            *(uint4*)(s_stg7 + gg*P_STG7 + c8) = __ldg(&src[idx]);
        }
    }
    __syncthreads();

    float y_local = 0.f;

    // ---- P6: y1 += sum relu(aG1 + beta @ bbG2) * HW1  (k16 x4 over z) ----
    {
        const int wm = w >> 2;      // 0..3 -> s block of 32
        const int wn = w & 3;       // 0..3 -> g block of 64
        const float* aG1p = g_aG1 + (size_t)b*NS*ND;
        float acc[2][8][4];
        #pragma unroll
        for (int mi=0;mi<2;mi++)
            #pragma unroll
            for (int f=0;f<8;f++)
                #pragma unroll
                for (int e=0;e<4;e++) acc[mi][f][e]=0.f;
        #pragma unroll
        for (int kz = 0; kz < 4; kz++) {
            uint32_t afr[2][4];
            #pragma unroll
            for (int mi = 0; mi < 2; mi++) {
                const bf16* ap = s_beta + (wm*32 + mi*16 + r)*P_BETA + kz*16 + 2*c;
                afr[mi][0]=ldb(ap); afr[mi][1]=ldb(ap+8*P_BETA);
                afr[mi][2]=ldb(ap+8); afr[mi][3]=ldb(ap+8*P_BETA+8);
            }
            #pragma unroll
            for (int f = 0; f < 8; f++) {
                const bf16* bp = s_bg2t + (wn*64 + f*8 + r)*P_BG2T + kz*16 + 2*c;
                uint32_t b0 = ldb(bp), b1 = ldb(bp+8);
                mmab(acc[0][f], afr[0][0],afr[0][1],afr[0][2],afr[0][3], b0,b1);
                mmab(acc[1][f], afr[1][0],afr[1][1],afr[1][2],afr[1][3], b0,b1);
            }
        }
        #pragma unroll
        for (int mi=0;mi<2;mi++)
            #pragma unroll
            for (int f=0;f<8;f++){
                int row0 = wm*32 + mi*16 + r;
                int col0 = wn*64 + f*8 + 2*c;
                float2 g0 = __ldg((const float2*)(aG1p + (size_t)row0*ND + col0));
                float2 g1 = __ldg((const float2*)(aG1p + (size_t)(row0+8)*ND + col0));
                float h0 = sHW[col0], h1 = sHW[col0+1];
                y_local += fmaxf(acc[mi][f][0] + g0.x, 0.f)*h0
                         + fmaxf(acc[mi][f][1] + g0.y, 0.f)*h1
                         + fmaxf(acc[mi][f][2] + g1.x, 0.f)*h0
                         + fmaxf(acc[mi][f][3] + g1.y, 0.f)*h1;
            }
    }

    // ---- P7: y2 += sum relu(bG1 + alpha^T @ aG2) * HW2  (k16 x8 over s) ----
    {
        const int wm = w >> 3;      // 0..1 -> z block of 32
        const int wn = w & 7;       // 0..7 -> g block of 32
        float acc[2][4][4];
        #pragma unroll
        for (int mi=0;mi<2;mi++)
            #pragma unroll
            for (int f=0;f<4;f++){
                int row0 = wm*32 + mi*16 + r;
                int col0 = wn*32 + f*8 + 2*c;
                int id0 = s_cid[row0], id1 = s_cid[row0+8];
                float2 u0 = __ldg((const float2*)(g_bg1 + (size_t)id0*ND + col0));
                float2 u1 = __ldg((const float2*)(g_bg1 + (size_t)id1*ND + col0));
                acc[mi][f][0]=u0.x; acc[mi][f][1]=u0.y;
                acc[mi][f][2]=u1.x; acc[mi][f][3]=u1.y;
            }
        #pragma unroll
        for (int ks = 0; ks < 8; ks++) {
            uint32_t afr[2][4];
            #pragma unroll
            for (int mi = 0; mi < 2; mi++) {
                const bf16* ap = s_alpt + (wm*32 + mi*16 + r)*P_ALPT + ks*16 + 2*c;
                afr[mi][0]=ldb(ap); afr[mi][1]=ldb(ap+8*P_ALPT);
                afr[mi][2]=ldb(ap+8); afr[mi][3]=ldb(ap+8*P_ALPT+8);
            }
            #pragma unroll
            for (int f = 0; f < 4; f++) {
                const bf16* bp = s_stg7 + (wn*32 + f*8 + r)*P_STG7 + ks*16 + 2*c;
                uint32_t b0 = ldb(bp), b1 = ldb(bp+8);
                mmab(acc[0][f], afr[0][0],afr[0][1],afr[0][2],afr[0][3], b0,b1);
                mmab(acc[1][f], afr[1][0],afr[1][1],afr[1][2],afr[1][3], b0,b1);
            }
        }
        #pragma unroll
        for (int mi=0;mi<2;mi++)
            #pragma unroll
            for (int f=0;f<4;f++){
                int col0 = wn*32 + f*8 + 2*c;
                float h0 = sHW[256+col0], h1 = sHW[256+col0+1];
                y_local += fmaxf(acc[mi][f][0], 0.f)*h0
                         + fmaxf(acc[mi][f][1], 0.f)*h1
                         + fmaxf(acc[mi][f][2], 0.f)*h0
                         + fmaxf(acc[mi][f][3], 0.f)*h1;
            }
    }
    __syncthreads();

    // ---- block reduce (16 warps) ----
    {
        #pragma unroll
        for (int off = 16; off >= 1; off >>= 1)
            y_local += __shfl_xor_sync(0xffffffffu, y_local, off);
        if (lane == 0) sRed[w] = y_local;
        __syncthreads();
        if (tid == 0) {
            float t = 0.f;
            #pragma unroll
            for (int ww = 0; ww < 16; ww++) t += sRed[ww];
            out[p] = t + __ldg(&Hb[0]);
        }
    }
}

// =========================================================================
extern "C" void kernel_launch(void* const* d_in, const int* in_sizes, int n_in,
                              void* d_out, int out_size)
{
    const int*   inptensor = (const int*)  d_in[0];
    const int*   cand      = (const int*)  d_in[1];
    const float* EmbA      = (const float*)d_in[4];
    const float* EmbB      = (const float*)d_in[5];
    const float* FW        = (const float*)d_in[6];
    const float* Fb        = (const float*)d_in[7];
    const float* GW        = (const float*)d_in[8];
    const float* Gb        = (const float*)d_in[9];
    const float* HW        = (const float*)d_in[10];
    const float* Hb        = (const float*)d_in[11];
    float*       out       = (float*)d_out;

    (void)in_sizes; (void)n_in; (void)out_size;

    const int smem1 = (64*257 + 16*64) * 4;    // 69888 B -> 2 CTAs/SM
    cudaFuncSetAttribute(tables_kernel, cudaFuncAttributeMaxDynamicSharedMemorySize, smem1);
    cudaFuncSetAttribute(pair_kernel,   cudaFuncAttributeMaxDynamicSharedMemorySize, SMEM_PAIR);

    tables_kernel<<<dim3(12, 2*NB + VOP/64), 256, smem1>>>(
        inptensor, EmbA, EmbB, FW, Fb, GW, Gb);
    pair_kernel<<<NB*NC, 512, SMEM_PAIR>>>(cand, HW, Hb, out);
}

// round 8
// speedup vs baseline: 5.0434x; 1.0003x over previous
#include <cuda_runtime.h>
#include <cuda_bf16.h>
#include <cstdint>

#define NB 32
#define NC 64
#define NS 128
#define NZ 64
#define ND 256
#define VO 5000
#define VOP 5120

typedef __nv_bfloat16 bf16;

// ---- pair-kernel smem byte offsets ----
#define OB_AM    0         // 67584 B
#define OB_BM    67584     // 33792 B
#define OB_BG2T  0         // 36864 B
#define OB_STG7  36864     // 69632 B
#define OB_E     106496    // e fp32 [128][68] = 34816
#define OB_BETA  141312    // beta bf16 [128][72] = 18432
#define OB_ALPT  159744    // alphaT bf16 [64][136] = 17408
#define OB_CID   177152    // 64 ints
#define OB_HW    177408    // 512 fp32
#define OB_RED   179456    // 16 fp32
#define SMEM_PAIR 179520

// pitches (elements)
#define P_AM   264
#define P_BM   264
#define P_E    68
#define P_BETA 72
#define P_BG2T 72
#define P_ALPT 136
#define P_STG7 136

// ---------------- device scratch ----------------
__device__ bf16  g_am  [NB*NS*ND];   // bf16 relu(a@FW+Fb)       [b][s][k]
__device__ float g_aG1 [NB*NS*ND];   // exact a@GW1+Gb           [b][s][g]
__device__ bf16  g_aG2T[NB*ND*NS];   // bf16 (a@GW2)^T           [b][g][s]
__device__ bf16  g_bm  [VOP*ND];     // bf16 relu(EmbB@FW+Fb)    [v][k]
__device__ float g_bg1 [VOP*ND];     // exact EmbB@GW1+Gb        [v][g]
__device__ bf16  g_bg2 [VOP*ND];     // bf16 EmbB@GW2            [v][g]

// ---------------- helpers ----------------
__device__ __forceinline__ uint32_t ldb(const bf16* p){
    return *reinterpret_cast<const uint32_t*>(p);
}
__device__ __forceinline__ uint32_t pkf(float a, float b){
    __nv_bfloat162 t = __floats2bfloat162_rn(a, b);
    return *reinterpret_cast<uint32_t*>(&t);
}
__device__ __forceinline__ uint32_t pkh(bf16 a, bf16 b){
    __nv_bfloat162 t = __halves2bfloat162(a, b);
    return *reinterpret_cast<uint32_t*>(&t);
}
__device__ __forceinline__ void mmab(float* d,
    uint32_t a0,uint32_t a1,uint32_t a2,uint32_t a3, uint32_t b0,uint32_t b1){
    asm volatile("mma.sync.aligned.m16n8k16.row.col.f32.bf16.bf16.f32 "
        "{%0,%1,%2,%3}, {%4,%5,%6,%7}, {%8,%9}, {%0,%1,%2,%3};\n"
        : "+f"(d[0]),"+f"(d[1]),"+f"(d[2]),"+f"(d[3])
        : "r"(a0),"r"(a1),"r"(a2),"r"(a3),"r"(b0),"r"(b1));
}

// =========================================================================
// Tables kernel (exact fp32 FFMA; bf16/fp32 outputs). 64-row tiles, 2 CTA/SM.
// grid=(12, 144): y<64 -> a-side (b=y>>1, half=y&1); else vocab tile rt=y-64.
// m = chunk>>2: 0 F+relu (bf16), 1 GW1+Gb (fp32), 2 GW2 (bf16; a-side -> g_aG2T
// via smem transpose, coalesced stores)
// =========================================================================
__global__ void __launch_bounds__(256) tables_kernel(
    const int*   __restrict__ inptensor,
    const float* __restrict__ EmbA,
    const float* __restrict__ EmbB,
    const float* __restrict__ FW,
    const float* __restrict__ Fb,
    const float* __restrict__ GW,
    const float* __restrict__ Gb)
{
    extern __shared__ float sm[];
    float* a_tile = sm;              // 64*257
    float* wst    = sm + 64*257;     // 16*64

    const int y     = blockIdx.y;
    const int chunk = blockIdx.x;
    const int m     = chunk >> 2;
    const int gbase = (chunk & 3) * 64;
    const int tid   = threadIdx.x;
    const bool aside = (y < 2*NB);

    if (aside) {
        const int b = y >> 1, sh = (y & 1) * 64;
        for (int s = 0; s < 64; s++) {
            int idx = __ldg(&inptensor[b*NS + sh + s]);
            a_tile[s*257 + tid] = __ldg(&EmbA[(size_t)idx*ND + tid]);
        }
    } else {
        const int rt = y - 2*NB;
        for (int s = 0; s < 64; s++) {
            int row = rt*64 + s;
            int rr = (row < VO) ? row : 0;
            a_tile[s*257 + tid] = __ldg(&EmbB[(size_t)rr*ND + tid]);
        }
    }
    __syncthreads();

    const int tr = tid >> 3;   // 0..31 (row group)
    const int tc = tid & 7;    // 0..7  (8 consecutive g per thread)

    float acc[2][8];
    #pragma unroll
    for (int i = 0; i < 2; i++)
        #pragma unroll
        for (int j = 0; j < 8; j++) acc[i][j] = 0.f;

    for (int k0 = 0; k0 < ND; k0 += 16) {
        #pragma unroll
        for (int t = 0; t < 4; t++) {
            int idx2 = tid + 256*t;
            int kk = idx2 >> 6, gg = idx2 & 63;
            int row = k0 + kk + (m == 2 ? 256 : 0);
            const float* Wsrc = (m == 0) ? FW : GW;
            wst[idx2] = __ldg(&Wsrc[row*256 + gbase + gg]);
        }
        __syncthreads();
        #pragma unroll
        for (int kk = 0; kk < 16; kk++) {
            float av0 = a_tile[tr*257 + k0 + kk];
            float av1 = a_tile[(tr + 32)*257 + k0 + kk];
            const float4* wp = (const float4*)(wst + kk*64 + tc*8);
            float4 w0 = wp[0], w1 = wp[1];
            float wv[8] = {w0.x,w0.y,w0.z,w0.w,w1.x,w1.y,w1.z,w1.w};
            #pragma unroll
            for (int j = 0; j < 8; j++) { acc[0][j] += av0*wv[j]; acc[1][j] += av1*wv[j]; }
        }
        __syncthreads();
    }

    float bias[8];
    #pragma unroll
    for (int j = 0; j < 8; j++) {
        int g = gbase + tc*8 + j;
        bias[j] = (m == 0) ? __ldg(&Fb[g]) : (m == 1 ? __ldg(&Gb[g]) : 0.f);
    }

    const int b_  = y >> 1, sh = (y & 1) * 64;
    const int rt  = y - 2*NB;

    if (m == 2 && aside) {
        // transpose through smem (a_tile dead), then coalesced store to g_aG2T
        bf16* tbuf = (bf16*)a_tile;              // [64 g][66 s] bf16, pitch 66
        #pragma unroll
        for (int i = 0; i < 2; i++) {
            int row = tr + 32*i;                 // local s (0..63)
            #pragma unroll
            for (int j = 0; j < 8; j++)
                tbuf[(tc*8 + j)*66 + row] = __float2bfloat16_rn(acc[i][j]);
        }
        __syncthreads();
        // each thread stores 16 contiguous s-values for one g row.
        // smem side is only 4-byte aligned (pitch 66 bf16 = 132 B) -> read as u32.
        int gl = tid >> 2;                       // 0..63
        int sc = (tid & 3) * 16;
        const uint32_t* src = (const uint32_t*)(tbuf + gl*66 + sc);
        uint32_t v[8];
        #pragma unroll
        for (int j = 0; j < 8; j++) v[j] = src[j];
        uint4* dst = (uint4*)(g_aG2T + ((size_t)b_*ND + gbase + gl)*NS + sh + sc);
        dst[0] = make_uint4(v[0],v[1],v[2],v[3]);
        dst[1] = make_uint4(v[4],v[5],v[6],v[7]);
        return;
    }

    #pragma unroll
    for (int i = 0; i < 2; i++) {
        int row = aside ? (sh + tr + 32*i) : (rt*64 + tr + 32*i);
        float v[8];
        #pragma unroll
        for (int j = 0; j < 8; j++) {
            v[j] = acc[i][j] + bias[j];
            if (m == 0) v[j] = fmaxf(v[j], 0.f);
        }
        if (m == 1) {
            float* outp = aside ? (g_aG1 + (size_t)b_*NS*ND) : g_bg1;
            float4* o4 = (float4*)(outp + (size_t)row*ND + gbase + tc*8);
            o4[0] = make_float4(v[0],v[1],v[2],v[3]);
            o4[1] = make_float4(v[4],v[5],v[6],v[7]);
        } else {
            bf16* outp = (m == 0)
                ? (aside ? (g_am + (size_t)b_*NS*ND) : g_bm)
                : g_bg2;   // m==2 b-side
            uint32_t u[4];
            #pragma unroll
            for (int j = 0; j < 4; j++) u[j] = pkf(v[2*j], v[2*j+1]);
            uint4* o4 = (uint4*)(outp + (size_t)row*ND + gbase + tc*8);
            *o4 = make_uint4(u[0],u[1],u[2],u[3]);
        }
    }
}

// =========================================================================
// Pair kernel: one CTA per (b,c). 512 threads / 16 warps. bf16 mma k16.
// =========================================================================
__global__ void __launch_bounds__(512) pair_kernel(
    const int*   __restrict__ cand,
    const float* __restrict__ HW,
    const float* __restrict__ Hb,
    float*       __restrict__ out)
{
    extern __shared__ char smc[];
    bf16*  s_am   = (bf16*) (smc + OB_AM);     // [128][264]
    bf16*  s_bm   = (bf16*) (smc + OB_BM);     // [64][264]
    bf16*  s_bg2t = (bf16*) (smc + OB_BG2T);   // [256][72]
    bf16*  s_stg7 = (bf16*) (smc + OB_STG7);   // [256][136]
    float* s_e    = (float*)(smc + OB_E);      // [128][68]
    bf16*  s_beta = (bf16*) (smc + OB_BETA);   // [128][72]
    bf16*  s_alpt = (bf16*) (smc + OB_ALPT);   // [64][136]
    int*   s_cid  = (int*)  (smc + OB_CID);
    float* sHW    = (float*)(smc + OB_HW);
    float* sRed   = (float*)(smc + OB_RED);

    const int tid  = threadIdx.x;
    const int p    = blockIdx.x;
    const int b    = p >> 6;
    const int w    = tid >> 5;
    const int lane = tid & 31;
    const int r    = lane >> 2;
    const int c    = lane & 3;

    if (tid < 256) { sHW[tid] = __ldg(&HW[tid]); sHW[tid+256] = __ldg(&HW[tid+256]); }
    if (tid < 64)  s_cid[tid] = __ldg(&cand[p*NZ + tid]);

    // ---- P1: stage a_m (full 128x256) + gather b_m rows ----
    {
        const uint4* src = (const uint4*)(g_am + (size_t)b*NS*ND);
        #pragma unroll
        for (int t = 0; t < 8; t++) {
            int idx = tid + 512*t;
            int row = idx >> 5, c8 = (idx & 31) * 8;
            *(uint4*)(s_am + row*P_AM + c8) = __ldg(&src[idx]);
        }
        #pragma unroll
        for (int t = 0; t < 4; t++) {
            int idx = tid + 512*t;
            int z = idx >> 5, c8 = (idx & 31) * 8;
            int id = __ldg(&cand[p*NZ + z]);
            *(uint4*)(s_bm + z*P_BM + c8) = __ldg((const uint4*)(g_bm + (size_t)id*ND + c8));
        }
    }
    __syncthreads();

    // ---- P3: e[s][z] = a_m @ b_m^T ----
    {
        const int wm = w >> 1;
        const int wn = w & 1;
        const int s0 = wm*16, zb = wn*32;
        float acc[4][4];
        #pragma unroll
        for (int f=0;f<4;f++){ acc[f][0]=0.f;acc[f][1]=0.f;acc[f][2]=0.f;acc[f][3]=0.f; }

        const bf16* ap0 = s_am + (s0 + r)*P_AM + 2*c;
        #pragma unroll 4
        for (int ks = 0; ks < 16; ks++) {
            const bf16* ap = ap0 + ks*16;
            uint32_t a0 = ldb(ap), a1 = ldb(ap + 8*P_AM), a2 = ldb(ap + 8), a3 = ldb(ap + 8*P_AM + 8);
            #pragma unroll
            for (int f = 0; f < 4; f++) {
                const bf16* bp = s_bm + (zb + f*8 + r)*P_BM + ks*16 + 2*c;
                mmab(acc[f], a0,a1,a2,a3, ldb(bp), ldb(bp+8));
            }
        }
        #pragma unroll
        for (int f = 0; f < 4; f++) {
            int col0 = zb + f*8 + 2*c;
            *(float2*)(s_e + (s0+r)*P_E + col0)   = make_float2(acc[f][0], acc[f][1]);
            *(float2*)(s_e + (s0+r+8)*P_E + col0) = make_float2(acc[f][2], acc[f][3]);
        }
    }
    __syncthreads();

    // ---- P4a: beta = softmax over z (rows) ----
    {
        #pragma unroll
        for (int rr = 0; rr < 8; rr++) {
            int s = w*8 + rr;
            float v0 = s_e[s*P_E + lane];
            float v1 = s_e[s*P_E + lane + 32];
            float mx = fmaxf(v0, v1);
            #pragma unroll
            for (int off = 16; off >= 1; off >>= 1)
                mx = fmaxf(mx, __shfl_xor_sync(0xffffffffu, mx, off));
            float e0 = expf(v0 - mx), e1 = expf(v1 - mx);
            float ss = e0 + e1;
            #pragma unroll
            for (int off = 16; off >= 1; off >>= 1)
                ss += __shfl_xor_sync(0xffffffffu, ss, off);
            float inv = 1.f / ss;
            s_beta[s*P_BETA + lane]      = __float2bfloat16_rn(e0 * inv);
            s_beta[s*P_BETA + lane + 32] = __float2bfloat16_rn(e1 * inv);
        }
    }

    // ---- P4b: alpha = softmax over s (cols) -> s_alpt transposed ----
    {
        const int z = tid >> 3, q = tid & 7;
        float ev[16];
        float mx = -1e30f;
        #pragma unroll
        for (int i = 0; i < 16; i++) {
            ev[i] = s_e[(q*16 + i)*P_E + z];
            mx = fmaxf(mx, ev[i]);
        }
        mx = fmaxf(mx, __shfl_xor_sync(0xffffffffu, mx, 1));
        mx = fmaxf(mx, __shfl_xor_sync(0xffffffffu, mx, 2));
        mx = fmaxf(mx, __shfl_xor_sync(0xffffffffu, mx, 4));
        float ss = 0.f;
        #pragma unroll
        for (int i = 0; i < 16; i++) { ev[i] = expf(ev[i] - mx); ss += ev[i]; }
        ss += __shfl_xor_sync(0xffffffffu, ss, 1);
        ss += __shfl_xor_sync(0xffffffffu, ss, 2);
        ss += __shfl_xor_sync(0xffffffffu, ss, 4);
        float inv = 1.f / ss;
        #pragma unroll
        for (int i = 0; i < 8; i++) {
            uint32_t u = pkf(ev[2*i]*inv, ev[2*i+1]*inv);
            *(uint32_t*)(s_alpt + z*P_ALPT + q*16 + 2*i) = u;
        }
    }

    // ---- gather bbG2^T + stage aG2^T ----
    {
        const int half = tid >> 8;
        const int g    = tid & 255;
        #pragma unroll
        for (int t = 0; t < 16; t++) {
            int z0 = (half*16 + t) * 2;
            int id0 = s_cid[z0], id1 = s_cid[z0+1];
            bf16 v0 = __ldg(g_bg2 + (size_t)id0*ND + g);
            bf16 v1 = __ldg(g_bg2 + (size_t)id1*ND + g);
            *(uint32_t*)(s_bg2t + g*P_BG2T + z0) = pkh(v0, v1);
        }
        const uint4* src = (const uint4*)(g_aG2T + (size_t)b*ND*NS);
        #pragma unroll
        for (int t = 0; t < 8; t++) {
            int idx = tid + 512*t;
            int gg = idx >> 4, c8 = (idx & 15) * 8;
            *(uint4*)(s_stg7 + gg*P_STG7 + c8) = __ldg(&src[idx]);
        }
    }
    __syncthreads();

    float y_local = 0.f;

    // ---- P6: y1 += sum relu(aG1 + beta @ bbG2) * HW1 ----
    {
        const int wm = w >> 2;
        const int wn = w & 3;
        const float* aG1p = g_aG1 + (size_t)b*NS*ND;
        float acc[2][8][4];
        #pragma unroll
        for (int mi=0;mi<2;mi++)
            #pragma unroll
            for (int f=0;f<8;f++)
                #pragma unroll
                for (int e=0;e<4;e++) acc[mi][f][e]=0.f;
        #pragma unroll
        for (int kz = 0; kz < 4; kz++) {
            uint32_t afr[2][4];
            #pragma unroll
            for (int mi = 0; mi < 2; mi++) {
                const bf16* ap = s_beta + (wm*32 + mi*16 + r)*P_BETA + kz*16 + 2*c;
                afr[mi][0]=ldb(ap); afr[mi][1]=ldb(ap+8*P_BETA);
                afr[mi][2]=ldb(ap+8); afr[mi][3]=ldb(ap+8*P_BETA+8);
            }
            #pragma unroll
            for (int f = 0; f < 8; f++) {
                const bf16* bp = s_bg2t + (wn*64 + f*8 + r)*P_BG2T + kz*16 + 2*c;
                uint32_t b0 = ldb(bp), b1 = ldb(bp+8);
                mmab(acc[0][f], afr[0][0],afr[0][1],afr[0][2],afr[0][3], b0,b1);
                mmab(acc[1][f], afr[1][0],afr[1][1],afr[1][2],afr[1][3], b0,b1);
            }
        }
        #pragma unroll
        for (int mi=0;mi<2;mi++)
            #pragma unroll
            for (int f=0;f<8;f++){
                int row0 = wm*32 + mi*16 + r;
                int col0 = wn*64 + f*8 + 2*c;
                float2 g0 = __ldg((const float2*)(aG1p + (size_t)row0*ND + col0));
                float2 g1 = __ldg((const float2*)(aG1p + (size_t)(row0+8)*ND + col0));
                float h0 = sHW[col0], h1 = sHW[col0+1];
                y_local += fmaxf(acc[mi][f][0] + g0.x, 0.f)*h0
                         + fmaxf(acc[mi][f][1] + g0.y, 0.f)*h1
                         + fmaxf(acc[mi][f][2] + g1.x, 0.f)*h0
                         + fmaxf(acc[mi][f][3] + g1.y, 0.f)*h1;
            }
    }

    // ---- P7: y2 += sum relu(bG1 + alpha^T @ aG2) * HW2 ----
    {
        const int wm = w >> 3;
        const int wn = w & 7;
        float acc[2][4][4];
        #pragma unroll
        for (int mi=0;mi<2;mi++)
            #pragma unroll
            for (int f=0;f<4;f++){
                int row0 = wm*32 + mi*16 + r;
                int col0 = wn*32 + f*8 + 2*c;
                int id0 = s_cid[row0], id1 = s_cid[row0+8];
                float2 u0 = __ldg((const float2*)(g_bg1 + (size_t)id0*ND + col0));
                float2 u1 = __ldg((const float2*)(g_bg1 + (size_t)id1*ND + col0));
                acc[mi][f][0]=u0.x; acc[mi][f][1]=u0.y;
                acc[mi][f][2]=u1.x; acc[mi][f][3]=u1.y;
            }
        #pragma unroll
        for (int ks = 0; ks < 8; ks++) {
            uint32_t afr[2][4];
            #pragma unroll
            for (int mi = 0; mi < 2; mi++) {
                const bf16* ap = s_alpt + (wm*32 + mi*16 + r)*P_ALPT + ks*16 + 2*c;
                afr[mi][0]=ldb(ap); afr[mi][1]=ldb(ap+8*P_ALPT);
                afr[mi][2]=ldb(ap+8); afr[mi][3]=ldb(ap+8*P_ALPT+8);
            }
            #pragma unroll
            for (int f = 0; f < 4; f++) {
                const bf16* bp = s_stg7 + (wn*32 + f*8 + r)*P_STG7 + ks*16 + 2*c;
                uint32_t b0 = ldb(bp), b1 = ldb(bp+8);
                mmab(acc[0][f], afr[0][0],afr[0][1],afr[0][2],afr[0][3], b0,b1);
                mmab(acc[1][f], afr[1][0],afr[1][1],afr[1][2],afr[1][3], b0,b1);
            }
        }
        #pragma unroll
        for (int mi=0;mi<2;mi++)
            #pragma unroll
            for (int f=0;f<4;f++){
                int col0 = wn*32 + f*8 + 2*c;
                float h0 = sHW[256+col0], h1 = sHW[256+col0+1];
                y_local += fmaxf(acc[mi][f][0], 0.f)*h0
                         + fmaxf(acc[mi][f][1], 0.f)*h1
                         + fmaxf(acc[mi][f][2], 0.f)*h0
                         + fmaxf(acc[mi][f][3], 0.f)*h1;
            }
    }
    __syncthreads();

    // ---- block reduce ----
    {
        #pragma unroll
        for (int off = 16; off >= 1; off >>= 1)
            y_local += __shfl_xor_sync(0xffffffffu, y_local, off);
        if (lane == 0) sRed[w] = y_local;
        __syncthreads();
        if (tid == 0) {
            float t = 0.f;
            #pragma unroll
            for (int ww = 0; ww < 16; ww++) t += sRed[ww];
            out[p] = t + __ldg(&Hb[0]);
        }
    }
}

// =========================================================================
extern "C" void kernel_launch(void* const* d_in, const int* in_sizes, int n_in,
                              void* d_out, int out_size)
{
    const int*   inptensor = (const int*)  d_in[0];
    const int*   cand      = (const int*)  d_in[1];
    const float* EmbA      = (const float*)d_in[4];
    const float* EmbB      = (const float*)d_in[5];
    const float* FW        = (const float*)d_in[6];
    const float* Fb        = (const float*)d_in[7];
    const float* GW        = (const float*)d_in[8];
    const float* Gb        = (const float*)d_in[9];
    const float* HW        = (const float*)d_in[10];
    const float* Hb        = (const float*)d_in[11];
    float*       out       = (float*)d_out;

    (void)in_sizes; (void)n_in; (void)out_size;

    const int smem1 = (64*257 + 16*64) * 4;    // 69888 B -> 2 CTAs/SM
    cudaFuncSetAttribute(tables_kernel, cudaFuncAttributeMaxDynamicSharedMemorySize, smem1);
    cudaFuncSetAttribute(pair_kernel,   cudaFuncAttributeMaxDynamicSharedMemorySize, SMEM_PAIR);

    tables_kernel<<<dim3(12, 2*NB + VOP/64), 256, smem1>>>(
        inptensor, EmbA, EmbB, FW, Fb, GW, Gb);
    pair_kernel<<<NB*NC, 512, SMEM_PAIR>>>(cand, HW, Hb, out);
}